// round 14
// baseline (speedup 1.0000x reference)
#include <cuda_runtime.h>
#include <cuda_bf16.h>
#include <math_constants.h>
#include <math.h>
#include <cstdint>

#define NN 50000
#define EE 800000
#define BB 64
#define DD 128
#define LL 4
#define HRD 640      /* D*(L+1) */
#define NOUT 10
#define BN_EPS 1e-5

// ---------------- scratch (device globals; no allocation allowed) ----------
__device__ __align__(16) float  g_hr[(size_t)NN * HRD];   // [x | h1 | h2 | h3 | h4]
__device__ __align__(16) float  g_pooled[NN * DD];
__device__ __align__(16) float  g_z1[NN * DD];
__device__ __align__(16) float  g_z2[NN * DD];
// per-(layer,linear) BN stat slots: [2l] = after mlp_w1, [2l+1] = after mlp_w2
__device__ double g_sumS[2 * LL][DD];
__device__ double g_sumQ[2 * LL][DD];
__device__ float  g_scores[NN];
__device__ __align__(16) float  g_gembp[4 * BB * HRD];    // 4 partials per graph
// pre-converted weights: W^T bf16 hi/lo, [n][k] row-major (plain)
__device__ __align__(16) unsigned short g_whiT[2 * LL][DD * DD];
__device__ __align__(16) unsigned short g_wloT[2 * LL][DD * DD];
// CSR scratch (g_cnt==0 at entry; scan re-zeroes + seeds cursors each call)
__device__ int g_cnt[NN];
__device__ int g_cur[NN];
__device__ int g_rowptr[NN + 1];
__device__ int g_esrc[EE];

// ---------------- HMMA m16n8k16 bf16 (baseline PTX, sm_80+) -----------------
__device__ __forceinline__ void mma16816(float& d0, float& d1, float& d2, float& d3,
                                         uint32_t a0, uint32_t a1, uint32_t a2, uint32_t a3,
                                         uint32_t b0, uint32_t b1) {
    asm volatile(
        "mma.sync.aligned.m16n8k16.row.col.f32.bf16.bf16.f32 "
        "{%0,%1,%2,%3}, {%4,%5,%6,%7}, {%8,%9}, {%0,%1,%2,%3};"
        : "+f"(d0), "+f"(d1), "+f"(d2), "+f"(d3)
        : "r"(a0), "r"(a1), "r"(a2), "r"(a3), "r"(b0), "r"(b1));
}

// ---------------- CSR construction ------------------------------------------
__global__ void hist_kernel(const int* __restrict__ dst) {
    int e = blockIdx.x * blockDim.x + threadIdx.x;
    if (e < EE) atomicAdd(&g_cnt[dst[e]], 1);
}

__global__ void __launch_bounds__(1024) scan_kernel() {
    __shared__ int wsum[32];
    __shared__ int carry_sh;
    int tid = threadIdx.x, lane = tid & 31, wid = tid >> 5;
    for (int i = tid; i < 2 * LL * DD; i += 1024) {
        (&g_sumS[0][0])[i] = 0.0;
        (&g_sumQ[0][0])[i] = 0.0;
    }
    if (tid == 0) carry_sh = 0;
    __syncthreads();
    for (int t = 0; t < 49; t++) {
        int g = t * 1024 + tid;
        int v = (g < NN) ? g_cnt[g] : 0;
        if (g < NN) g_cnt[g] = 0;
        int carry = carry_sh;
        int s = v;
#pragma unroll
        for (int off = 1; off < 32; off <<= 1) {
            int u = __shfl_up_sync(0xffffffffu, s, off);
            if (lane >= off) s += u;
        }
        if (lane == 31) wsum[wid] = s;
        __syncthreads();
        if (wid == 0) {
            int ws = wsum[lane];
#pragma unroll
            for (int off = 1; off < 32; off <<= 1) {
                int u = __shfl_up_sync(0xffffffffu, ws, off);
                if (lane >= off) ws += u;
            }
            wsum[lane] = ws;
        }
        __syncthreads();
        int wpre = (wid == 0) ? 0 : wsum[wid - 1];
        if (g < NN) {
            int rp = carry + wpre + s - v;
            g_rowptr[g] = rp;
            g_cur[g] = rp;
        }
        __syncthreads();
        if (tid == 1023) carry_sh = carry + wsum[31];
        __syncthreads();
    }
    if (tid == 0) g_rowptr[NN] = EE;
}

__global__ void scatter_kernel(const int* __restrict__ src,
                               const int* __restrict__ dst) {
    int e = blockIdx.x * blockDim.x + threadIdx.x;
    if (e >= EE) return;
    int d = dst[e];
    int p = atomicAdd(&g_cur[d], 1);
    g_esrc[p] = src[e];
}

// ---------------- weight pre-convert: W[k][n] -> W^T bf16 hi/lo [n][k] -------
__global__ void wconv_kernel(const float* __restrict__ w1,
                             const float* __restrict__ w2) {
    int idx = blockIdx.x * 256 + threadIdx.x;
    if (idx >= 2 * LL * DD * DD) return;
    int mat = idx >> 14;          // 0..7: 2l + s
    int e = idx & 16383;
    int k = e >> 7, n = e & 127;
    int l = mat >> 1, s = mat & 1;
    const float* W = (s ? w2 : w1) + (size_t)l * DD * DD;
    float v = W[k * DD + n];
    __nv_bfloat16 h = __float2bfloat16(v);
    __nv_bfloat16 lo = __float2bfloat16(v - __bfloat162float(h));
    g_whiT[mat][n * DD + k] = __bfloat16_as_ushort(h);
    g_wloT[mat][n * DD + k] = __bfloat16_as_ushort(lo);
}

// ---------------- fused aggregation (unchanged, passing) ---------------------
template <int SLAB>
__global__ void __launch_bounds__(256) aggregate_kernel(
    const float* __restrict__ x, const float* __restrict__ eps,
    const float* __restrict__ aw, const float* __restrict__ ab,
    const float* __restrict__ gamma, const float* __restrict__ beta) {
    __shared__ float bnA[DD], bnC[DD];
    int tid = threadIdx.x;
    if (SLAB > 0) {
        if (tid < DD) {
            double m = g_sumS[2 * (SLAB - 1) + 1][tid] / (double)NN;
            double v = g_sumQ[2 * (SLAB - 1) + 1][tid] / (double)NN - m * m;
            float a = gamma[tid] * rsqrtf((float)(v + (double)BN_EPS));
            bnA[tid] = a;
            bnC[tid] = beta[tid] - (float)m * a;
        }
        __syncthreads();
    }
    int idx = blockIdx.x * 256 + tid;
    int i = idx >> 5, lane = idx & 31;
    if (i >= NN) return;

    float4 a4, c4;
    if (SLAB > 0) {
        a4 = reinterpret_cast<const float4*>(bnA)[lane];
        c4 = reinterpret_cast<const float4*>(bnC)[lane];
    }
    const float* hsrc = (SLAB == 0) ? x : g_z2;

    auto loadh = [&](int s) -> float4 {
        float4 v = reinterpret_cast<const float4*>(hsrc + (size_t)s * DD)[lane];
        if (SLAB > 0) {
            v.x = fmaxf(fmaf(a4.x, v.x, c4.x), 0.f);
            v.y = fmaxf(fmaf(a4.y, v.y, c4.y), 0.f);
            v.z = fmaxf(fmaf(a4.z, v.z, c4.z), 0.f);
            v.w = fmaxf(fmaf(a4.w, v.w, c4.w), 0.f);
        }
        return v;
    };

    int beg = g_rowptr[i], end = g_rowptr[i + 1];
    float4 acc = make_float4(0.f, 0.f, 0.f, 0.f);
    int e = beg;
    for (; e + 3 < end; e += 4) {
        int s0 = g_esrc[e], s1 = g_esrc[e + 1], s2 = g_esrc[e + 2], s3 = g_esrc[e + 3];
        float4 v0 = loadh(s0), v1 = loadh(s1), v2 = loadh(s2), v3 = loadh(s3);
        acc.x += (v0.x + v1.x) + (v2.x + v3.x);
        acc.y += (v0.y + v1.y) + (v2.y + v3.y);
        acc.z += (v0.z + v1.z) + (v2.z + v3.z);
        acc.w += (v0.w + v1.w) + (v2.w + v3.w);
    }
    for (; e < end; e++) {
        float4 v0 = loadh(g_esrc[e]);
        acc.x += v0.x; acc.y += v0.y; acc.z += v0.z; acc.w += v0.w;
    }

    float4 h = loadh(i);
    reinterpret_cast<float4*>(g_hr + (size_t)i * HRD + (size_t)SLAB * DD)[lane] = h;
    float4 w = reinterpret_cast<const float4*>(aw)[SLAB * 32 + lane];
    float s = h.x * w.x + h.y * w.y + h.z * w.z + h.w * w.w;
#pragma unroll
    for (int off = 16; off; off >>= 1) s += __shfl_down_sync(0xffffffffu, s, off);
    if (lane == 0) {
        if (SLAB == 0) g_scores[i] = s + ab[0];
        else           g_scores[i] += s;
    }
    float sc = 1.0f + eps[SLAB];
    acc.x = fmaf(sc, h.x, acc.x);
    acc.y = fmaf(sc, h.y, acc.y);
    acc.z = fmaf(sc, h.z, acc.z);
    acc.w = fmaf(sc, h.w, acc.w);
    reinterpret_cast<float4*>(g_pooled + (size_t)i * DD)[lane] = acc;
}

// h_4 = relu(affine(z2)) -> hr slab 4; accumulate final score segment
__global__ void __launch_bounds__(256) apply_h_kernel(int l,
                                                      const float* __restrict__ aw,
                                                      const float* __restrict__ gamma,
                                                      const float* __restrict__ beta) {
    __shared__ float bnA[DD], bnC[DD];
    int tid = threadIdx.x;
    if (tid < DD) {
        double m = g_sumS[2 * l + 1][tid] / (double)NN;
        double v = g_sumQ[2 * l + 1][tid] / (double)NN - m * m;
        float a = gamma[tid] * rsqrtf((float)(v + (double)BN_EPS));
        bnA[tid] = a;
        bnC[tid] = beta[tid] - (float)m * a;
    }
    __syncthreads();
    int idx = blockIdx.x * blockDim.x + tid;
    if (idx >= NN * 32) return;
    int i = idx >> 5, c = idx & 31;
    float4 z = reinterpret_cast<const float4*>(g_z2 + (size_t)i * DD)[c];
    float4 a = reinterpret_cast<const float4*>(bnA)[c];
    float4 b = reinterpret_cast<const float4*>(bnC)[c];
    float4 o;
    o.x = fmaxf(fmaf(a.x, z.x, b.x), 0.f);
    o.y = fmaxf(fmaf(a.y, z.y, b.y), 0.f);
    o.z = fmaxf(fmaf(a.z, z.z, b.z), 0.f);
    o.w = fmaxf(fmaf(a.w, z.w, b.w), 0.f);
    reinterpret_cast<float4*>(g_hr + (size_t)i * HRD + (size_t)(l + 1) * DD)[c] = o;
    float4 w = reinterpret_cast<const float4*>(aw)[(l + 1) * 32 + c];
    float s = o.x * w.x + o.y * w.y + o.z * w.z + o.w * w.w;
#pragma unroll
    for (int off = 16; off; off >>= 1) s += __shfl_down_sync(0xffffffffu, s, off);
    if ((tid & 31) == 0) g_scores[i] += s;
}

// ---------------- HMMA GEMM: C[128 rows,128] = A @ W + b ---------------------
// bf16 3-product split: Ahi*Whi + Alo*Whi + Ahi*Wlo, fp32 register accumulate.
// smem holds Ahi/Alo/Whi (108KB -> 2 blocks/SM); Wlo fragments via __ldg (L1).
#define TSTRIDE 272                      /* bytes per 128-col bf16 row */
#define OFF_AHI  0
#define OFF_ALO  (128 * TSTRIDE)
#define OFF_WHI  (2 * 128 * TSTRIDE)
#define OFF_BIAS (3 * 128 * TSTRIDE)               /* 512 B  */
#define OFF_REDS (OFF_BIAS + 512)                  /* 1024 B */
#define OFF_REDQ (OFF_REDS + 1024)                 /* 1024 B */
#define OFF_BNA  (OFF_REDQ + 1024)                 /* 512 B  */
#define OFF_BNC  (OFF_BNA + 512)                   /* 512 B  */
#define TC_SMEM  (OFF_BNC + 512)                   /* 108032 */

template <bool SECOND>
__global__ void __launch_bounds__(256, 2) hmma_gemm_kernel(const float* __restrict__ bias,
                                                           const float* __restrict__ gamma,
                                                           const float* __restrict__ beta,
                                                           int l) {
    extern __shared__ char sm[];
    float* s_bias = (float*)(sm + OFF_BIAS);
    double* redS = (double*)(sm + OFF_REDS);
    double* redQ = (double*)(sm + OFF_REDQ);
    float* bnA = (float*)(sm + OFF_BNA);
    float* bnC = (float*)(sm + OFF_BNC);
    int tid = threadIdx.x, w = tid >> 5, lane = tid & 31;
    int grp = lane >> 2, tig = lane & 3;
    const int mat = 2 * l + (SECOND ? 1 : 0);

    if (tid < DD) {
        redS[tid] = 0.0; redQ[tid] = 0.0;
        s_bias[tid] = bias[tid];
        if (SECOND) {
            double m = g_sumS[2 * l][tid] / (double)NN;
            double v = g_sumQ[2 * l][tid] / (double)NN - m * m;
            float a = gamma[tid] * rsqrtf((float)(v + (double)BN_EPS));
            bnA[tid] = a;
            bnC[tid] = beta[tid] - (float)m * a;
        }
    }
    __syncthreads();

    // W^T hi copy into padded smem (each of 256 threads: half a row = 64 bf16)
    {
        int r = tid >> 1, half = tid & 1;
        const uint4* srcH = (const uint4*)(g_whiT[mat] + r * DD + half * 64);
        uint4* dstH = (uint4*)(sm + OFF_WHI + r * TSTRIDE + half * 128);
#pragma unroll
        for (int j = 0; j < 8; j++) dstH[j] = srcH[j];
    }
    // A tile: load fp32, (opt affine+relu), split bf16 hi/lo into padded smem
    {
        const float4* A4 = (const float4*)(SECOND ? g_z1 : g_pooled);
        int row0 = blockIdx.x * 128;
#pragma unroll
        for (int j = 0; j < 16; j++) {
            int idx = tid + j * 256;          // float4 index over 128x32
            int r = idx >> 5, c4 = idx & 31;  // c4: float4 column
            int row = row0 + r;
            float4 v = make_float4(0.f, 0.f, 0.f, 0.f);
            if (row < NN) {
                v = A4[(size_t)row * 32 + c4];
                if (SECOND) {
                    float4 ba = ((const float4*)bnA)[c4];
                    float4 bc = ((const float4*)bnC)[c4];
                    v.x = fmaxf(fmaf(ba.x, v.x, bc.x), 0.f);
                    v.y = fmaxf(fmaf(ba.y, v.y, bc.y), 0.f);
                    v.z = fmaxf(fmaf(ba.z, v.z, bc.z), 0.f);
                    v.w = fmaxf(fmaf(ba.w, v.w, bc.w), 0.f);
                }
            }
            __nv_bfloat16 h0 = __float2bfloat16(v.x), h1 = __float2bfloat16(v.y);
            __nv_bfloat16 h2 = __float2bfloat16(v.z), h3 = __float2bfloat16(v.w);
            __nv_bfloat16 l0 = __float2bfloat16(v.x - __bfloat162float(h0));
            __nv_bfloat16 l1 = __float2bfloat16(v.y - __bfloat162float(h1));
            __nv_bfloat16 l2 = __float2bfloat16(v.z - __bfloat162float(h2));
            __nv_bfloat16 l3 = __float2bfloat16(v.w - __bfloat162float(h3));
            uint2 hw, lw;
            hw.x = (uint32_t)__bfloat16_as_ushort(h0) | ((uint32_t)__bfloat16_as_ushort(h1) << 16);
            hw.y = (uint32_t)__bfloat16_as_ushort(h2) | ((uint32_t)__bfloat16_as_ushort(h3) << 16);
            lw.x = (uint32_t)__bfloat16_as_ushort(l0) | ((uint32_t)__bfloat16_as_ushort(l1) << 16);
            lw.y = (uint32_t)__bfloat16_as_ushort(l2) | ((uint32_t)__bfloat16_as_ushort(l3) << 16);
            *(uint2*)(sm + OFF_AHI + r * TSTRIDE + c4 * 8) = hw;
            *(uint2*)(sm + OFF_ALO + r * TSTRIDE + c4 * 8) = lw;
        }
    }
    __syncthreads();

    // mainloop: warp w owns rows [w*16, w*16+16), all 128 columns (16 n-tiles)
    float acc[16][4];
#pragma unroll
    for (int nt = 0; nt < 16; nt++)
#pragma unroll
        for (int p = 0; p < 4; p++) acc[nt][p] = 0.f;

    const char* pAh0 = sm + OFF_AHI + (w * 16 + grp) * TSTRIDE;
    const char* pAh1 = pAh0 + 8 * TSTRIDE;
    const char* pAl0 = sm + OFF_ALO + (w * 16 + grp) * TSTRIDE;
    const char* pAl1 = pAl0 + 8 * TSTRIDE;
    const char* pWh = sm + OFF_WHI + grp * TSTRIDE;
    const uint32_t* WL = (const uint32_t*)g_wloT[mat];   // word idx = n*64 + k/2

#pragma unroll 1
    for (int ks = 0; ks < 8; ks++) {
        int kb = ks * 32 + tig * 4;       // byte offset of k = ks*16 + tig*2
        uint32_t ah0 = *(const uint32_t*)(pAh0 + kb);
        uint32_t ah1 = *(const uint32_t*)(pAh1 + kb);
        uint32_t ah2 = *(const uint32_t*)(pAh0 + kb + 16);
        uint32_t ah3 = *(const uint32_t*)(pAh1 + kb + 16);
        uint32_t al0 = *(const uint32_t*)(pAl0 + kb);
        uint32_t al1 = *(const uint32_t*)(pAl1 + kb);
        uint32_t al2 = *(const uint32_t*)(pAl0 + kb + 16);
        uint32_t al3 = *(const uint32_t*)(pAl1 + kb + 16);
        int wlbase = grp * 64 + ks * 8 + tig;   // word index for n=grp, this ks
#pragma unroll
        for (int nt = 0; nt < 16; nt++) {
            uint32_t bh0 = *(const uint32_t*)(pWh + nt * 8 * TSTRIDE + kb);
            uint32_t bh1 = *(const uint32_t*)(pWh + nt * 8 * TSTRIDE + kb + 16);
            uint32_t bl0 = __ldg(&WL[wlbase + nt * 512]);        // (nt*8+grp)*64
            uint32_t bl1 = __ldg(&WL[wlbase + nt * 512 + 4]);
            mma16816(acc[nt][0], acc[nt][1], acc[nt][2], acc[nt][3],
                     ah0, ah1, ah2, ah3, bh0, bh1);
            mma16816(acc[nt][0], acc[nt][1], acc[nt][2], acc[nt][3],
                     al0, al1, al2, al3, bh0, bh1);
            mma16816(acc[nt][0], acc[nt][1], acc[nt][2], acc[nt][3],
                     ah0, ah1, ah2, ah3, bl0, bl1);
        }
    }

    // epilogue: bias, C store, fp64 column stats
    float* C = SECOND ? g_z2 : g_z1;
    const int slot_out = 2 * l + (SECOND ? 1 : 0);
    int m0 = blockIdx.x * 128 + w * 16 + grp;
    int m1 = m0 + 8;
    bool v0 = m0 < NN, v1 = m1 < NN;
#pragma unroll
    for (int nt = 0; nt < 16; nt++) {
        int n0 = nt * 8 + tig * 2;
        float b0 = s_bias[n0], b1 = s_bias[n0 + 1];
        float o00 = acc[nt][0] + b0, o01 = acc[nt][1] + b1;
        float o10 = acc[nt][2] + b0, o11 = acc[nt][3] + b1;
        if (v0) *(float2*)(C + (size_t)m0 * DD + n0) = make_float2(o00, o01);
        if (v1) *(float2*)(C + (size_t)m1 * DD + n0) = make_float2(o10, o11);
        float cs0 = (v0 ? o00 : 0.f) + (v1 ? o10 : 0.f);
        float cs1 = (v0 ? o01 : 0.f) + (v1 ? o11 : 0.f);
        float cq0 = (v0 ? o00 * o00 : 0.f) + (v1 ? o10 * o10 : 0.f);
        float cq1 = (v0 ? o01 * o01 : 0.f) + (v1 ? o11 * o11 : 0.f);
#pragma unroll
        for (int off = 16; off >= 4; off >>= 1) {
            cs0 += __shfl_down_sync(0xffffffffu, cs0, off);
            cs1 += __shfl_down_sync(0xffffffffu, cs1, off);
            cq0 += __shfl_down_sync(0xffffffffu, cq0, off);
            cq1 += __shfl_down_sync(0xffffffffu, cq1, off);
        }
        if (lane < 4) {
            int nn = nt * 8 + lane * 2;
            atomicAdd(&redS[nn], (double)cs0);
            atomicAdd(&redS[nn + 1], (double)cs1);
            atomicAdd(&redQ[nn], (double)cq0);
            atomicAdd(&redQ[nn + 1], (double)cq1);
        }
    }
    __syncthreads();
    if (tid < DD) {
        atomicAdd(&g_sumS[slot_out][tid], redS[tid]);
        atomicAdd(&g_sumQ[slot_out][tid], redQ[tid]);
    }
}

// ---------------- attention pooling + head (unchanged) ----------------------
#define ECHUNK 512
__global__ void __launch_bounds__(256) gemb_part_kernel(const int* __restrict__ gid) {
    __shared__ int s_beg, s_end;
    __shared__ float red[32];
    __shared__ float s_mx, s_dn;
    __shared__ float ecache[ECHUNK];
    int b = blockIdx.x >> 2, q = blockIdx.x & 3, t = threadIdx.x;
    int lane = t & 31, wid = t >> 5;
    if (t == 0) {
        int lo = 0, hi = NN;
        while (lo < hi) { int m = (lo + hi) >> 1; if (gid[m] < b) lo = m + 1; else hi = m; }
        s_beg = lo;
        lo = 0; hi = NN;
        while (lo < hi) { int m = (lo + hi) >> 1; if (gid[m] < b + 1) lo = m + 1; else hi = m; }
        s_end = lo;
    }
    __syncthreads();
    int beg = s_beg, end = s_end;

    float mx = -CUDART_INF_F;
    for (int i = beg + t; i < end; i += 256) mx = fmaxf(mx, g_scores[i]);
#pragma unroll
    for (int off = 16; off; off >>= 1) mx = fmaxf(mx, __shfl_xor_sync(0xffffffffu, mx, off));
    if (lane == 0) red[wid] = mx;
    __syncthreads();
    if (wid == 0) {
        float m2 = (lane < 8) ? red[lane] : -CUDART_INF_F;
#pragma unroll
        for (int off = 4; off; off >>= 1) m2 = fmaxf(m2, __shfl_xor_sync(0xffffffffu, m2, off));
        if (lane == 0) s_mx = m2;
    }
    __syncthreads();
    float smax = s_mx;

    float dn = 0.f;
    for (int i = beg + t; i < end; i += 256) dn += expf(g_scores[i] - smax);
#pragma unroll
    for (int off = 16; off; off >>= 1) dn += __shfl_xor_sync(0xffffffffu, dn, off);
    if (lane == 0) red[wid] = dn;
    __syncthreads();
    if (wid == 0) {
        float d2 = (lane < 8) ? red[lane] : 0.f;
#pragma unroll
        for (int off = 4; off; off >>= 1) d2 += __shfl_xor_sync(0xffffffffu, d2, off);
        if (lane == 0) s_dn = d2;
    }
    __syncthreads();
    float denom = s_dn;

    int len = end - beg;
    int qb = beg + (int)(((long long)len * q) >> 2);
    int qe = beg + (int)(((long long)len * (q + 1)) >> 2);

    float4 acc = make_float4(0.f, 0.f, 0.f, 0.f);
    for (int chunk = qb; chunk < qe; chunk += ECHUNK) {
        int ce = chunk + ECHUNK < qe ? chunk + ECHUNK : qe;
        for (int i = chunk + t; i < ce; i += 256)
            ecache[i - chunk] = expf(g_scores[i] - smax) / denom;
        __syncthreads();
        if (t < HRD / 4) {
            for (int i = chunk; i < ce; i++) {
                float c = ecache[i - chunk];
                float4 v = reinterpret_cast<const float4*>(g_hr + (size_t)i * HRD)[t];
                acc.x = fmaf(c, v.x, acc.x);
                acc.y = fmaf(c, v.y, acc.y);
                acc.z = fmaf(c, v.z, acc.z);
                acc.w = fmaf(c, v.w, acc.w);
            }
        }
        __syncthreads();
    }
    if (t < HRD / 4)
        reinterpret_cast<float4*>(g_gembp + (size_t)blockIdx.x * HRD)[t] = acc;
}

__global__ void final_kernel(const float* __restrict__ pi,
                             const float* __restrict__ pi_w,
                             const float* __restrict__ pi_b,
                             const float* __restrict__ out_w,
                             const float* __restrict__ out_b,
                             float* __restrict__ out) {
    __shared__ float pie[16];
    int b = blockIdx.x, tid = threadIdx.x;
    if (tid < 16) {
        float a = pi_b[tid];
#pragma unroll
        for (int k = 0; k < 25; k++) a = fmaf(pi[b * 25 + k], pi_w[k * 16 + tid], a);
        pie[tid] = fmaxf(a, 0.f);
    }
    __syncthreads();
    int o = tid >> 5, lane = tid & 31;
    float acc = 0.f;
    const float* g0 = g_gembp + (size_t)(b * 4 + 0) * HRD;
    const float* g1 = g_gembp + (size_t)(b * 4 + 1) * HRD;
    const float* g2 = g_gembp + (size_t)(b * 4 + 2) * HRD;
    const float* g3 = g_gembp + (size_t)(b * 4 + 3) * HRD;
    for (int j = lane; j < HRD; j += 32) {
        float ge = (g0[j] + g1[j]) + (g2[j] + g3[j]);
        acc = fmaf(ge, out_w[j * NOUT + o], acc);
    }
    if (lane < 16) acc = fmaf(pie[lane], out_w[(HRD + lane) * NOUT + o], acc);
#pragma unroll
    for (int off = 16; off; off >>= 1) acc += __shfl_down_sync(0xffffffffu, acc, off);
    if (lane == 0) out[b * NOUT + o] = acc + out_b[o];
}

// ---------------- launch -----------------------------------------------------
extern "C" void kernel_launch(void* const* d_in, const int* in_sizes, int n_in,
                              void* d_out, int out_size) {
    const float* x    = (const float*)d_in[0];
    const float* pi   = (const float*)d_in[1];
    const float* eps  = (const float*)d_in[2];
    const float* w1   = (const float*)d_in[3];
    const float* b1   = (const float*)d_in[4];
    const float* bng1 = (const float*)d_in[5];
    const float* bnb1 = (const float*)d_in[6];
    const float* w2   = (const float*)d_in[7];
    const float* b2   = (const float*)d_in[8];
    const float* bng  = (const float*)d_in[9];
    const float* bnb  = (const float*)d_in[10];
    const float* aw   = (const float*)d_in[11];
    const float* ab   = (const float*)d_in[12];
    const float* pw   = (const float*)d_in[13];
    const float* pb   = (const float*)d_in[14];
    const float* ow   = (const float*)d_in[15];
    const float* ob   = (const float*)d_in[16];
    const int*   ei   = (const int*)d_in[17];
    const int*   gid  = (const int*)d_in[18];
    const int* src = ei;
    const int* dst = ei + EE;
    float* out = (float*)d_out;

    cudaFuncSetAttribute(hmma_gemm_kernel<false>,
                         cudaFuncAttributeMaxDynamicSharedMemorySize, TC_SMEM);
    cudaFuncSetAttribute(hmma_gemm_kernel<true>,
                         cudaFuncAttributeMaxDynamicSharedMemorySize, TC_SMEM);

    const int ELT_BLOCKS = (NN * 32 + 255) / 256;          // 6250
    const int TC_BLOCKS = (NN + 127) / 128;                // 391
    const int EDGE_BLK = (EE + 255) / 256;                 // 3125

    hist_kernel<<<EDGE_BLK, 256>>>(dst);                   // 1
    scan_kernel<<<1, 1024>>>();                            // 2
    scatter_kernel<<<EDGE_BLK, 256>>>(src, dst);           // 3

    aggregate_kernel<0><<<ELT_BLOCKS, 256>>>(x, eps, aw, ab, nullptr, nullptr); // 4 (profiled)
    wconv_kernel<<<512, 256>>>(w1, w2);                    // 5

    hmma_gemm_kernel<false><<<TC_BLOCKS, 256, TC_SMEM>>>(b1, nullptr, nullptr, 0);
    hmma_gemm_kernel<true><<<TC_BLOCKS, 256, TC_SMEM>>>(b2, bng1, bnb1, 0);
    aggregate_kernel<1><<<ELT_BLOCKS, 256>>>(x, eps, aw, ab, bng + 0 * DD, bnb + 0 * DD);
    hmma_gemm_kernel<false><<<TC_BLOCKS, 256, TC_SMEM>>>(b1 + 1 * DD, nullptr, nullptr, 1);
    hmma_gemm_kernel<true><<<TC_BLOCKS, 256, TC_SMEM>>>(b2 + 1 * DD, bng1 + 1 * DD, bnb1 + 1 * DD, 1);
    aggregate_kernel<2><<<ELT_BLOCKS, 256>>>(x, eps, aw, ab, bng + 1 * DD, bnb + 1 * DD);
    hmma_gemm_kernel<false><<<TC_BLOCKS, 256, TC_SMEM>>>(b1 + 2 * DD, nullptr, nullptr, 2);
    hmma_gemm_kernel<true><<<TC_BLOCKS, 256, TC_SMEM>>>(b2 + 2 * DD, bng1 + 2 * DD, bnb1 + 2 * DD, 2);
    aggregate_kernel<3><<<ELT_BLOCKS, 256>>>(x, eps, aw, ab, bng + 2 * DD, bnb + 2 * DD);
    hmma_gemm_kernel<false><<<TC_BLOCKS, 256, TC_SMEM>>>(b1 + 3 * DD, nullptr, nullptr, 3);
    hmma_gemm_kernel<true><<<TC_BLOCKS, 256, TC_SMEM>>>(b2 + 3 * DD, bng1 + 3 * DD, bnb1 + 3 * DD, 3);
    apply_h_kernel<<<ELT_BLOCKS, 256>>>(3, aw, bng + 3 * DD, bnb + 3 * DD);

    gemb_part_kernel<<<4 * BB, 256>>>(gid);
    final_kernel<<<BB, 320>>>(pi, pw, pb, ow, ob, out);
}

// round 15
// speedup vs baseline: 1.1902x; 1.1902x over previous
#include <cuda_runtime.h>
#include <math_constants.h>
#include <math.h>

#define NN 50000
#define EE 800000
#define BB 64
#define DD 128
#define LL 4
#define HRD 640      /* D*(L+1) */
#define NOUT 10
#define BN_EPS 1e-5

#define TILE_R 176   /* 285 blocks @ 2/SM = 0.96 waves; proven family */
#define ASTRIDE 132  /* padded smem row stride: rg groups hit distinct banks */
#define RPT (TILE_R / 16)   /* 11 rows per thread */
#define QParts 8     /* gemb partials per graph */

// ---------------- scratch (device globals; no allocation allowed) ----------
__device__ __align__(16) float  g_hr[(size_t)NN * HRD];   // [x | h1 | h2 | h3 | h4]
__device__ __align__(16) float  g_pooled[NN * DD];
__device__ __align__(16) float  g_z1[NN * DD];
__device__ __align__(16) float  g_z2[NN * DD];
// per-(layer,linear) BN stat slots: [2l] = after mlp_w1, [2l+1] = after mlp_w2
__device__ double g_sumS[2 * LL][DD];
__device__ double g_sumQ[2 * LL][DD];
__device__ float  g_scores[NN];
__device__ __align__(16) float  g_gembp[QParts * BB * HRD];  // 8 partials per graph
// CSR scratch. Invariants across calls (graph replays):
//   g_cnt == 0 at call entry (zeroed by scan each call; zero at module load)
//   g_cur is seeded to rowptr by scan each call BEFORE scatter uses it
__device__ int g_cnt[NN];
__device__ int g_cur[NN];
__device__ int g_rowptr[NN + 1];
__device__ int g_esrc[EE];

// ---------------- packed f32x2 helpers (Blackwell) --------------------------
__device__ __forceinline__ void ffma2(unsigned long long& acc,
                                      unsigned long long a,
                                      unsigned long long b) {
    asm("fma.rn.f32x2 %0, %1, %2, %0;" : "+l"(acc) : "l"(a), "l"(b));
}
__device__ __forceinline__ unsigned long long splat2(float a) {
    unsigned long long r;
    asm("mov.b64 %0, {%1, %1};" : "=l"(r) : "f"(a));
    return r;
}
__device__ __forceinline__ float2 unpack2(unsigned long long v) {
    float2 r;
    asm("mov.b64 {%0, %1}, %2;" : "=f"(r.x), "=f"(r.y) : "l"(v));
    return r;
}

// ---------------- CSR construction ------------------------------------------
__global__ void hist_kernel(const int* __restrict__ dst) {
    int e = blockIdx.x * blockDim.x + threadIdx.x;
    if (e < EE) atomicAdd(&g_cnt[dst[e]], 1);
}

// single-block hierarchical scan over 50000 counts.
// Writes rowptr, seeds g_cur = rowptr, zeroes g_cnt, zeroes BN stat slots.
__global__ void __launch_bounds__(1024) scan_kernel() {
    __shared__ int wsum[32];
    __shared__ int carry_sh;
    int tid = threadIdx.x, lane = tid & 31, wid = tid >> 5;
    // zero BN stat slots (deterministic per call -> replay safe)
    for (int i = tid; i < 2 * LL * DD; i += 1024) {
        (&g_sumS[0][0])[i] = 0.0;
        (&g_sumQ[0][0])[i] = 0.0;
    }
    if (tid == 0) carry_sh = 0;
    __syncthreads();
    for (int t = 0; t < 49; t++) {
        int g = t * 1024 + tid;
        int v = (g < NN) ? g_cnt[g] : 0;
        if (g < NN) g_cnt[g] = 0;
        int carry = carry_sh;
        int s = v;
#pragma unroll
        for (int off = 1; off < 32; off <<= 1) {
            int u = __shfl_up_sync(0xffffffffu, s, off);
            if (lane >= off) s += u;
        }
        if (lane == 31) wsum[wid] = s;
        __syncthreads();
        if (wid == 0) {
            int ws = wsum[lane];
#pragma unroll
            for (int off = 1; off < 32; off <<= 1) {
                int u = __shfl_up_sync(0xffffffffu, ws, off);
                if (lane >= off) ws += u;
            }
            wsum[lane] = ws;
        }
        __syncthreads();
        int wpre = (wid == 0) ? 0 : wsum[wid - 1];
        if (g < NN) {
            int rp = carry + wpre + s - v;
            g_rowptr[g] = rp;
            g_cur[g] = rp;          // scatter cursor seeded fresh every call
        }
        __syncthreads();
        if (tid == 1023) carry_sh = carry + wsum[31];
        __syncthreads();
    }
    if (tid == 0) g_rowptr[NN] = EE;
}

__global__ void scatter_kernel(const int* __restrict__ src,
                               const int* __restrict__ dst) {
    int e = blockIdx.x * blockDim.x + threadIdx.x;
    if (e >= EE) return;
    int d = dst[e];
    int p = atomicAdd(&g_cur[d], 1);   // cursor pre-seeded to rowptr[d]
    g_esrc[p] = src[e];
}

// ---------------- fused aggregation ------------------------------------------
// aggregate<SLAB>:
//   SLAB==0: h = x (passthrough).   SLAB>=1: h = relu(bnA*z2 + bnC) on the fly
// For node i: pooled[i] = sum_nbr h[src] + (1+eps[SLAB])*h[i];
// writes h[i] into hr slab SLAB; accumulates attention score segment.
template <int SLAB>
__global__ void __launch_bounds__(256) aggregate_kernel(
    const float* __restrict__ x, const float* __restrict__ eps,
    const float* __restrict__ aw, const float* __restrict__ ab,
    const float* __restrict__ gamma, const float* __restrict__ beta) {
    __shared__ float bnA[DD], bnC[DD];
    int tid = threadIdx.x;
    if (SLAB > 0) {
        if (tid < DD) {
            double m = g_sumS[2 * (SLAB - 1) + 1][tid] / (double)NN;
            double v = g_sumQ[2 * (SLAB - 1) + 1][tid] / (double)NN - m * m;
            float a = gamma[tid] * rsqrtf((float)(v + (double)BN_EPS));
            bnA[tid] = a;
            bnC[tid] = beta[tid] - (float)m * a;
        }
        __syncthreads();
    }
    int idx = blockIdx.x * 256 + tid;
    int i = idx >> 5, lane = idx & 31;
    if (i >= NN) return;

    float4 a4, c4;
    if (SLAB > 0) {
        a4 = reinterpret_cast<const float4*>(bnA)[lane];
        c4 = reinterpret_cast<const float4*>(bnC)[lane];
    }
    const float* hsrc = (SLAB == 0) ? x : g_z2;

    auto loadh = [&](int s) -> float4 {
        float4 v = reinterpret_cast<const float4*>(hsrc + (size_t)s * DD)[lane];
        if (SLAB > 0) {
            v.x = fmaxf(fmaf(a4.x, v.x, c4.x), 0.f);
            v.y = fmaxf(fmaf(a4.y, v.y, c4.y), 0.f);
            v.z = fmaxf(fmaf(a4.z, v.z, c4.z), 0.f);
            v.w = fmaxf(fmaf(a4.w, v.w, c4.w), 0.f);
        }
        return v;
    };

    int beg = g_rowptr[i], end = g_rowptr[i + 1];
    float4 acc = make_float4(0.f, 0.f, 0.f, 0.f);
    int e = beg;
    for (; e + 3 < end; e += 4) {
        int s0 = g_esrc[e], s1 = g_esrc[e + 1], s2 = g_esrc[e + 2], s3 = g_esrc[e + 3];
        float4 v0 = loadh(s0), v1 = loadh(s1), v2 = loadh(s2), v3 = loadh(s3);
        acc.x += (v0.x + v1.x) + (v2.x + v3.x);
        acc.y += (v0.y + v1.y) + (v2.y + v3.y);
        acc.z += (v0.z + v1.z) + (v2.z + v3.z);
        acc.w += (v0.w + v1.w) + (v2.w + v3.w);
    }
    for (; e < end; e++) {
        float4 v0 = loadh(g_esrc[e]);
        acc.x += v0.x; acc.y += v0.y; acc.z += v0.z; acc.w += v0.w;
    }

    // self term: h_i, hr-slab write, score segment, pooled
    float4 h = loadh(i);
    reinterpret_cast<float4*>(g_hr + (size_t)i * HRD + (size_t)SLAB * DD)[lane] = h;
    float4 w = reinterpret_cast<const float4*>(aw)[SLAB * 32 + lane];
    float s = h.x * w.x + h.y * w.y + h.z * w.z + h.w * w.w;
#pragma unroll
    for (int off = 16; off; off >>= 1) s += __shfl_down_sync(0xffffffffu, s, off);
    if (lane == 0) {
        if (SLAB == 0) g_scores[i] = s + ab[0];
        else           g_scores[i] += s;
    }
    float sc = 1.0f + eps[SLAB];
    acc.x = fmaf(sc, h.x, acc.x);
    acc.y = fmaf(sc, h.y, acc.y);
    acc.z = fmaf(sc, h.z, acc.z);
    acc.w = fmaf(sc, h.w, acc.w);
    reinterpret_cast<float4*>(g_pooled + (size_t)i * DD)[lane] = acc;
}

// h_4 = relu(affine(z2)) -> hr slab 4; accumulate final score segment (l=3)
__global__ void __launch_bounds__(256) apply_h_kernel(int l,
                                                      const float* __restrict__ aw,
                                                      const float* __restrict__ gamma,
                                                      const float* __restrict__ beta) {
    __shared__ float bnA[DD], bnC[DD];
    int tid = threadIdx.x;
    if (tid < DD) {
        double m = g_sumS[2 * l + 1][tid] / (double)NN;
        double v = g_sumQ[2 * l + 1][tid] / (double)NN - m * m;
        float a = gamma[tid] * rsqrtf((float)(v + (double)BN_EPS));
        bnA[tid] = a;
        bnC[tid] = beta[tid] - (float)m * a;
    }
    __syncthreads();
    int idx = blockIdx.x * blockDim.x + tid;
    if (idx >= NN * 32) return;
    int i = idx >> 5, c = idx & 31;
    float4 z = reinterpret_cast<const float4*>(g_z2 + (size_t)i * DD)[c];
    float4 a = reinterpret_cast<const float4*>(bnA)[c];
    float4 b = reinterpret_cast<const float4*>(bnC)[c];
    float4 o;
    o.x = fmaxf(fmaf(a.x, z.x, b.x), 0.f);
    o.y = fmaxf(fmaf(a.y, z.y, b.y), 0.f);
    o.z = fmaxf(fmaf(a.z, z.z, b.z), 0.f);
    o.w = fmaxf(fmaf(a.w, z.w, b.w), 0.f);
    reinterpret_cast<float4*>(g_hr + (size_t)i * HRD + (size_t)(l + 1) * DD)[c] = o;
    float4 w = reinterpret_cast<const float4*>(aw)[(l + 1) * 32 + c];
    float s = o.x * w.x + o.y * w.y + o.z * w.z + o.w * w.w;
#pragma unroll
    for (int off = 16; off; off >>= 1) s += __shfl_down_sync(0xffffffffu, s, off);
    if ((tid & 31) == 0) g_scores[i] += s;
}

// ---------------- GEMM (176 x 128) @ W[128,128] + b; col stats in fp64 -------
// SECOND=false: A = g_pooled (plain), C = g_z1, stats -> slot 2l
// SECOND=true : A = relu(affine(g_z1)) from slot 2l, C = g_z2, stats -> slot 2l+1
// Mainloop software-pipelines W: next-k LDG issued before current-k FFMA2s.
#define GEMM_SMEM (TILE_R * ASTRIDE * 4 + 2 * DD * 8 + 2 * DD * 4)

template <bool SECOND>
__global__ void __launch_bounds__(256, 2) gemm128_kernel(const float* __restrict__ W,
                                                         const float* __restrict__ bias,
                                                         const float* __restrict__ gamma,
                                                         const float* __restrict__ beta,
                                                         int l) {
    extern __shared__ float smem[];
    float* Ash = smem;                                        // TILE_R x ASTRIDE
    double* redS = reinterpret_cast<double*>(smem + TILE_R * ASTRIDE);
    double* redQ = redS + DD;
    float* bnA = reinterpret_cast<float*>(redQ + DD);
    float* bnC = bnA + DD;

    float* C = SECOND ? g_z2 : g_z1;
    const int slot_out = SECOND ? (2 * l + 1) : (2 * l);

    int tid = threadIdx.x;
    if (tid < DD) {
        redS[tid] = 0.0; redQ[tid] = 0.0;
        if (SECOND) {
            double m = g_sumS[2 * l][tid] / (double)NN;
            double v = g_sumQ[2 * l][tid] / (double)NN - m * m;
            float a = gamma[tid] * rsqrtf((float)(v + (double)BN_EPS));
            bnA[tid] = a;
            bnC[tid] = beta[tid] - (float)m * a;
        }
    }
    __syncthreads();

    int row0 = blockIdx.x * TILE_R;
    {
        const float* A = SECOND ? g_z1 : g_pooled;
#pragma unroll
        for (int ii = 0; ii < TILE_R * 32 / 256; ii++) {
            int i = tid + ii * 256;             // float4 index over tile
            int r = i >> 5, c4 = i & 31;
            int row = row0 + r;
            float4 v = make_float4(0.f, 0.f, 0.f, 0.f);
            if (row < NN) {
                v = *reinterpret_cast<const float4*>(A + (size_t)row * DD + c4 * 4);
                if (SECOND) {
                    float4 ba = reinterpret_cast<const float4*>(bnA)[c4];
                    float4 bc = reinterpret_cast<const float4*>(bnC)[c4];
                    v.x = fmaxf(fmaf(ba.x, v.x, bc.x), 0.f);
                    v.y = fmaxf(fmaf(ba.y, v.y, bc.y), 0.f);
                    v.z = fmaxf(fmaf(ba.z, v.z, bc.z), 0.f);
                    v.w = fmaxf(fmaf(ba.w, v.w, bc.w), 0.f);
                }
            }
            *reinterpret_cast<float4*>(Ash + r * ASTRIDE + c4 * 4) = v;
        }
    }
    __syncthreads();

    int cg = tid & 15;   // 8 columns: 8*cg .. 8*cg+7
    int rg = tid >> 4;   // rows rg*RPT .. rg*RPT+RPT-1
    const float* arow = Ash + rg * RPT * ASTRIDE;
    const ulonglong2* Wg = reinterpret_cast<const ulonglong2*>(W);

    unsigned long long acc[RPT][4];
#pragma unroll
    for (int r = 0; r < RPT; r++)
#pragma unroll
        for (int p = 0; p < 4; p++) acc[r][p] = 0ull;

    // software-pipelined W: prefetch k+1 before computing k
    ulonglong2 wA = __ldg(&Wg[cg * 2]);
    ulonglong2 wB = __ldg(&Wg[cg * 2 + 1]);
#pragma unroll 2
    for (int k = 0; k < DD - 1; k++) {
        ulonglong2 nA = __ldg(&Wg[(k + 1) * 32 + cg * 2]);
        ulonglong2 nB = __ldg(&Wg[(k + 1) * 32 + cg * 2 + 1]);
#pragma unroll
        for (int r = 0; r < RPT; r++) {
            unsigned long long a2 = splat2(arow[r * ASTRIDE + k]);
            ffma2(acc[r][0], a2, wA.x);
            ffma2(acc[r][1], a2, wA.y);
            ffma2(acc[r][2], a2, wB.x);
            ffma2(acc[r][3], a2, wB.y);
        }
        wA = nA; wB = nB;
    }
#pragma unroll
    for (int r = 0; r < RPT; r++) {       // tail k = DD-1
        unsigned long long a2 = splat2(arow[r * ASTRIDE + (DD - 1)]);
        ffma2(acc[r][0], a2, wA.x);
        ffma2(acc[r][1], a2, wA.y);
        ffma2(acc[r][2], a2, wB.x);
        ffma2(acc[r][3], a2, wB.y);
    }

    float bs[8];
#pragma unroll
    for (int j = 0; j < 8; j++) bs[j] = bias[cg * 8 + j];

    float cs[8], cq[8];
#pragma unroll
    for (int j = 0; j < 8; j++) { cs[j] = 0.f; cq[j] = 0.f; }

#pragma unroll
    for (int r = 0; r < RPT; r++) {
        int row = row0 + rg * RPT + r;
        if (row >= NN) continue;
        float o[8];
#pragma unroll
        for (int p = 0; p < 4; p++) {
            float2 u = unpack2(acc[r][p]);
            o[2 * p]     = u.x + bs[2 * p];
            o[2 * p + 1] = u.y + bs[2 * p + 1];
        }
        float4* cp = reinterpret_cast<float4*>(C + (size_t)row * DD + cg * 8);
        cp[0] = make_float4(o[0], o[1], o[2], o[3]);
        cp[1] = make_float4(o[4], o[5], o[6], o[7]);
#pragma unroll
        for (int j = 0; j < 8; j++) {
            cs[j] += o[j];
            cq[j] += o[j] * o[j];
        }
    }
    __syncthreads();
#pragma unroll
    for (int j = 0; j < 8; j++) {
        atomicAdd(&redS[cg * 8 + j], (double)cs[j]);
        atomicAdd(&redQ[cg * 8 + j], (double)cq[j]);
    }
    __syncthreads();
    if (tid < DD) {
        atomicAdd(&g_sumS[slot_out][tid], redS[tid]);
        atomicAdd(&g_sumQ[slot_out][tid], redQ[tid]);
    }
}

// ---------------- attention pooling + head ----------------------------------
// QParts blocks per graph; each computes segment max+denom (redundant, cheap)
// and its 1/QParts share of the weighted sum. Atomic-free.
#define ECHUNK 512
__global__ void __launch_bounds__(256) gemb_part_kernel(const int* __restrict__ gid) {
    __shared__ int s_beg, s_end;
    __shared__ float red[32];
    __shared__ float s_mx, s_dn;
    __shared__ float ecache[ECHUNK];
    int b = blockIdx.x / QParts, q = blockIdx.x % QParts, t = threadIdx.x;
    int lane = t & 31, wid = t >> 5;
    if (t == 0) {
        int lo = 0, hi = NN;
        while (lo < hi) { int m = (lo + hi) >> 1; if (gid[m] < b) lo = m + 1; else hi = m; }
        s_beg = lo;
        lo = 0; hi = NN;
        while (lo < hi) { int m = (lo + hi) >> 1; if (gid[m] < b + 1) lo = m + 1; else hi = m; }
        s_end = lo;
    }
    __syncthreads();
    int beg = s_beg, end = s_end;

    float mx = -CUDART_INF_F;
    for (int i = beg + t; i < end; i += 256) mx = fmaxf(mx, g_scores[i]);
#pragma unroll
    for (int off = 16; off; off >>= 1) mx = fmaxf(mx, __shfl_xor_sync(0xffffffffu, mx, off));
    if (lane == 0) red[wid] = mx;
    __syncthreads();
    if (wid == 0) {
        float m2 = (lane < 8) ? red[lane] : -CUDART_INF_F;
#pragma unroll
        for (int off = 4; off; off >>= 1) m2 = fmaxf(m2, __shfl_xor_sync(0xffffffffu, m2, off));
        if (lane == 0) s_mx = m2;
    }
    __syncthreads();
    float smax = s_mx;

    float dn = 0.f;
    for (int i = beg + t; i < end; i += 256) dn += expf(g_scores[i] - smax);
#pragma unroll
    for (int off = 16; off; off >>= 1) dn += __shfl_xor_sync(0xffffffffu, dn, off);
    if (lane == 0) red[wid] = dn;
    __syncthreads();
    if (wid == 0) {
        float d2 = (lane < 8) ? red[lane] : 0.f;
#pragma unroll
        for (int off = 4; off; off >>= 1) d2 += __shfl_xor_sync(0xffffffffu, d2, off);
        if (lane == 0) s_dn = d2;
    }
    __syncthreads();
    float denom = s_dn;

    int len = end - beg;
    int qb = beg + (int)(((long long)len * q) / QParts);
    int qe = beg + (int)(((long long)len * (q + 1)) / QParts);

    float4 acc = make_float4(0.f, 0.f, 0.f, 0.f);
    for (int chunk = qb; chunk < qe; chunk += ECHUNK) {
        int ce = chunk + ECHUNK < qe ? chunk + ECHUNK : qe;
        for (int i = chunk + t; i < ce; i += 256)
            ecache[i - chunk] = expf(g_scores[i] - smax) / denom;
        __syncthreads();
        if (t < HRD / 4) {
            for (int i = chunk; i < ce; i++) {
                float c = ecache[i - chunk];
                float4 v = reinterpret_cast<const float4*>(g_hr + (size_t)i * HRD)[t];
                acc.x = fmaf(c, v.x, acc.x);
                acc.y = fmaf(c, v.y, acc.y);
                acc.z = fmaf(c, v.z, acc.z);
                acc.w = fmaf(c, v.w, acc.w);
            }
        }
        __syncthreads();
    }
    if (t < HRD / 4)
        reinterpret_cast<float4*>(g_gembp + (size_t)blockIdx.x * HRD)[t] = acc;
}

__global__ void final_kernel(const float* __restrict__ pi,
                             const float* __restrict__ pi_w,
                             const float* __restrict__ pi_b,
                             const float* __restrict__ out_w,
                             const float* __restrict__ out_b,
                             float* __restrict__ out) {
    __shared__ float pie[16];
    int b = blockIdx.x, tid = threadIdx.x;
    if (tid < 16) {
        float a = pi_b[tid];
#pragma unroll
        for (int k = 0; k < 25; k++) a = fmaf(pi[b * 25 + k], pi_w[k * 16 + tid], a);
        pie[tid] = fmaxf(a, 0.f);
    }
    __syncthreads();
    int o = tid >> 5, lane = tid & 31;
    float acc = 0.f;
    const float* gp = g_gembp + (size_t)b * QParts * HRD;
    for (int j = lane; j < HRD; j += 32) {
        float ge = 0.f;
#pragma unroll
        for (int p = 0; p < QParts; p++) ge += gp[p * HRD + j];
        acc = fmaf(ge, out_w[j * NOUT + o], acc);
    }
    if (lane < 16) acc = fmaf(pie[lane], out_w[(HRD + lane) * NOUT + o], acc);
#pragma unroll
    for (int off = 16; off; off >>= 1) acc += __shfl_down_sync(0xffffffffu, acc, off);
    if (lane == 0) out[b * NOUT + o] = acc + out_b[o];
}

// ---------------- launch -----------------------------------------------------
extern "C" void kernel_launch(void* const* d_in, const int* in_sizes, int n_in,
                              void* d_out, int out_size) {
    const float* x    = (const float*)d_in[0];
    const float* pi   = (const float*)d_in[1];
    const float* eps  = (const float*)d_in[2];
    const float* w1   = (const float*)d_in[3];
    const float* b1   = (const float*)d_in[4];
    const float* bng1 = (const float*)d_in[5];
    const float* bnb1 = (const float*)d_in[6];
    const float* w2   = (const float*)d_in[7];
    const float* b2   = (const float*)d_in[8];
    const float* bng  = (const float*)d_in[9];
    const float* bnb  = (const float*)d_in[10];
    const float* aw   = (const float*)d_in[11];
    const float* ab   = (const float*)d_in[12];
    const float* pw   = (const float*)d_in[13];
    const float* pb   = (const float*)d_in[14];
    const float* ow   = (const float*)d_in[15];
    const float* ob   = (const float*)d_in[16];
    const int*   ei   = (const int*)d_in[17];
    const int*   gid  = (const int*)d_in[18];
    const int* src = ei;
    const int* dst = ei + EE;
    float* out = (float*)d_out;

    cudaFuncSetAttribute(gemm128_kernel<false>,
                         cudaFuncAttributeMaxDynamicSharedMemorySize, GEMM_SMEM);
    cudaFuncSetAttribute(gemm128_kernel<true>,
                         cudaFuncAttributeMaxDynamicSharedMemorySize, GEMM_SMEM);

    const int ELT_BLOCKS = (NN * 32 + 255) / 256;          // 6250
    const int GEMM_BLOCKS = (NN + TILE_R - 1) / TILE_R;    // 285
    const int EDGE_BLK = (EE + 255) / 256;                 // 3125

    // ---- CSR by dst; g_cnt==0 at entry; scan zeroes stats + seeds cursors ----
    hist_kernel<<<EDGE_BLK, 256>>>(dst);                   // launch 1
    scan_kernel<<<1, 1024>>>();                            // launch 2
    scatter_kernel<<<EDGE_BLK, 256>>>(src, dst);           // launch 3

    // layer 0
    aggregate_kernel<0><<<ELT_BLOCKS, 256>>>(x, eps, aw, ab, nullptr, nullptr); // launch 4 (profiled)
    gemm128_kernel<false><<<GEMM_BLOCKS, 256, GEMM_SMEM>>>(w1, b1, nullptr, nullptr, 0);
    gemm128_kernel<true><<<GEMM_BLOCKS, 256, GEMM_SMEM>>>(w2, b2, bng1, bnb1, 0);
    // layer 1
    aggregate_kernel<1><<<ELT_BLOCKS, 256>>>(x, eps, aw, ab, bng + 0 * DD, bnb + 0 * DD);
    gemm128_kernel<false><<<GEMM_BLOCKS, 256, GEMM_SMEM>>>(w1 + 1 * DD * DD, b1 + 1 * DD, nullptr, nullptr, 1);
    gemm128_kernel<true><<<GEMM_BLOCKS, 256, GEMM_SMEM>>>(w2 + 1 * DD * DD, b2 + 1 * DD, bng1 + 1 * DD, bnb1 + 1 * DD, 1);
    // layer 2
    aggregate_kernel<2><<<ELT_BLOCKS, 256>>>(x, eps, aw, ab, bng + 1 * DD, bnb + 1 * DD);
    gemm128_kernel<false><<<GEMM_BLOCKS, 256, GEMM_SMEM>>>(w1 + 2 * DD * DD, b1 + 2 * DD, nullptr, nullptr, 2);
    gemm128_kernel<true><<<GEMM_BLOCKS, 256, GEMM_SMEM>>>(w2 + 2 * DD * DD, b2 + 2 * DD, bng1 + 2 * DD, bnb1 + 2 * DD, 2);
    // layer 3
    aggregate_kernel<3><<<ELT_BLOCKS, 256>>>(x, eps, aw, ab, bng + 2 * DD, bnb + 2 * DD);
    gemm128_kernel<false><<<GEMM_BLOCKS, 256, GEMM_SMEM>>>(w1 + 3 * DD * DD, b1 + 3 * DD, nullptr, nullptr, 3);
    gemm128_kernel<true><<<GEMM_BLOCKS, 256, GEMM_SMEM>>>(w2 + 3 * DD * DD, b2 + 3 * DD, bng1 + 3 * DD, bnb1 + 3 * DD, 3);
    // slab 4 (h_4) + final score segment
    apply_h_kernel<<<ELT_BLOCKS, 256>>>(3, aw, bng + 3 * DD, bnb + 3 * DD);

    gemb_part_kernel<<<QParts * BB, 256>>>(gid);
    final_kernel<<<BB, 320>>>(pi, pw, pb, ow, ob, out);
}

// round 16
// speedup vs baseline: 1.2081x; 1.0151x over previous
#include <cuda_runtime.h>
#include <math_constants.h>
#include <math.h>

#define NN 50000
#define EE 800000
#define BB 64
#define DD 128
#define LL 4
#define HRD 640      /* D*(L+1) */
#define NOUT 10
#define BN_EPS 1e-5

#define TILE_R 176   /* 285 blocks @ 2/SM = 0.96 waves; proven family */
#define ASTRIDE 132  /* padded smem row stride: rg groups hit distinct banks */
#define RPT (TILE_R / 16)   /* 11 rows per thread */
#define QParts 8     /* gemb partials per graph */

// ---------------- scratch (device globals; no allocation allowed) ----------
__device__ __align__(16) float  g_hr[(size_t)NN * HRD];   // [x | h1 | h2 | h3 | h4]
__device__ __align__(16) float  g_pooled[NN * DD];
__device__ __align__(16) float  g_z1[NN * DD];
__device__ __align__(16) float  g_z2[NN * DD];
// per-(layer,linear) BN stat slots: [2l] = after mlp_w1, [2l+1] = after mlp_w2
__device__ double g_sumS[2 * LL][DD];
__device__ double g_sumQ[2 * LL][DD];
__device__ float  g_scores[NN];
__device__ __align__(16) float  g_gembp[QParts * BB * HRD];  // 8 partials per graph
// CSR scratch. Invariants across calls (graph replays):
//   g_cnt == 0 at call entry (zeroed by scan each call; zero at module load)
//   g_cur is seeded to rowptr by scan each call BEFORE scatter uses it
__device__ int g_cnt[NN];
__device__ int g_cur[NN];
__device__ int g_rowptr[NN + 1];
__device__ int g_esrc[EE];

// ---------------- packed f32x2 helpers (Blackwell) --------------------------
__device__ __forceinline__ void ffma2(unsigned long long& acc,
                                      unsigned long long a,
                                      unsigned long long b) {
    asm("fma.rn.f32x2 %0, %1, %2, %0;" : "+l"(acc) : "l"(a), "l"(b));
}
__device__ __forceinline__ unsigned long long splat2(float a) {
    unsigned long long r;
    asm("mov.b64 %0, {%1, %1};" : "=l"(r) : "f"(a));
    return r;
}
__device__ __forceinline__ float2 unpack2(unsigned long long v) {
    float2 r;
    asm("mov.b64 {%0, %1}, %2;" : "=f"(r.x), "=f"(r.y) : "l"(v));
    return r;
}

// ---------------- CSR construction ------------------------------------------
__global__ void hist_kernel(const int* __restrict__ dst) {
    int e = blockIdx.x * blockDim.x + threadIdx.x;
    if (e < EE) atomicAdd(&g_cnt[dst[e]], 1);
}

// single-block hierarchical scan over 50000 counts.
// Writes rowptr, seeds g_cur = rowptr, zeroes g_cnt, zeroes BN stat slots.
__global__ void __launch_bounds__(1024) scan_kernel() {
    __shared__ int wsum[32];
    __shared__ int carry_sh;
    int tid = threadIdx.x, lane = tid & 31, wid = tid >> 5;
    // zero BN stat slots (deterministic per call -> replay safe)
    for (int i = tid; i < 2 * LL * DD; i += 1024) {
        (&g_sumS[0][0])[i] = 0.0;
        (&g_sumQ[0][0])[i] = 0.0;
    }
    if (tid == 0) carry_sh = 0;
    __syncthreads();
    for (int t = 0; t < 49; t++) {
        int g = t * 1024 + tid;
        int v = (g < NN) ? g_cnt[g] : 0;
        if (g < NN) g_cnt[g] = 0;
        int carry = carry_sh;
        int s = v;
#pragma unroll
        for (int off = 1; off < 32; off <<= 1) {
            int u = __shfl_up_sync(0xffffffffu, s, off);
            if (lane >= off) s += u;
        }
        if (lane == 31) wsum[wid] = s;
        __syncthreads();
        if (wid == 0) {
            int ws = wsum[lane];
#pragma unroll
            for (int off = 1; off < 32; off <<= 1) {
                int u = __shfl_up_sync(0xffffffffu, ws, off);
                if (lane >= off) ws += u;
            }
            wsum[lane] = ws;
        }
        __syncthreads();
        int wpre = (wid == 0) ? 0 : wsum[wid - 1];
        if (g < NN) {
            int rp = carry + wpre + s - v;
            g_rowptr[g] = rp;
            g_cur[g] = rp;          // scatter cursor seeded fresh every call
        }
        __syncthreads();
        if (tid == 1023) carry_sh = carry + wsum[31];
        __syncthreads();
    }
    if (tid == 0) g_rowptr[NN] = EE;
}

__global__ void scatter_kernel(const int* __restrict__ src,
                               const int* __restrict__ dst) {
    int e = blockIdx.x * blockDim.x + threadIdx.x;
    if (e >= EE) return;
    int d = dst[e];
    int p = atomicAdd(&g_cur[d], 1);   // cursor pre-seeded to rowptr[d]
    g_esrc[p] = src[e];
}

// ---------------- fused aggregation ------------------------------------------
// aggregate<SLAB>:
//   SLAB==0: h = x (passthrough).   SLAB>=1: h = relu(bnA*z2 + bnC) on the fly
// For node i: pooled[i] = sum_nbr h[src] + (1+eps[SLAB])*h[i];
// writes h[i] into hr slab SLAB; accumulates attention score segment.
// Edge loop unrolled 8-deep (two 4-trees) for MLP against L2 latency.
template <int SLAB>
__global__ void __launch_bounds__(256) aggregate_kernel(
    const float* __restrict__ x, const float* __restrict__ eps,
    const float* __restrict__ aw, const float* __restrict__ ab,
    const float* __restrict__ gamma, const float* __restrict__ beta) {
    __shared__ float bnA[DD], bnC[DD];
    int tid = threadIdx.x;
    if (SLAB > 0) {
        if (tid < DD) {
            double m = g_sumS[2 * (SLAB - 1) + 1][tid] / (double)NN;
            double v = g_sumQ[2 * (SLAB - 1) + 1][tid] / (double)NN - m * m;
            float a = gamma[tid] * rsqrtf((float)(v + (double)BN_EPS));
            bnA[tid] = a;
            bnC[tid] = beta[tid] - (float)m * a;
        }
        __syncthreads();
    }
    int idx = blockIdx.x * 256 + tid;
    int i = idx >> 5, lane = idx & 31;
    if (i >= NN) return;

    float4 a4, c4;
    if (SLAB > 0) {
        a4 = reinterpret_cast<const float4*>(bnA)[lane];
        c4 = reinterpret_cast<const float4*>(bnC)[lane];
    }
    const float* hsrc = (SLAB == 0) ? x : g_z2;

    auto loadh = [&](int s) -> float4 {
        float4 v = reinterpret_cast<const float4*>(hsrc + (size_t)s * DD)[lane];
        if (SLAB > 0) {
            v.x = fmaxf(fmaf(a4.x, v.x, c4.x), 0.f);
            v.y = fmaxf(fmaf(a4.y, v.y, c4.y), 0.f);
            v.z = fmaxf(fmaf(a4.z, v.z, c4.z), 0.f);
            v.w = fmaxf(fmaf(a4.w, v.w, c4.w), 0.f);
        }
        return v;
    };

    int beg = g_rowptr[i], end = g_rowptr[i + 1];
    float4 acc = make_float4(0.f, 0.f, 0.f, 0.f);
    float4 acc2 = make_float4(0.f, 0.f, 0.f, 0.f);
    int e = beg;
    for (; e + 7 < end; e += 8) {
        int s0 = g_esrc[e],     s1 = g_esrc[e + 1], s2 = g_esrc[e + 2], s3 = g_esrc[e + 3];
        int s4 = g_esrc[e + 4], s5 = g_esrc[e + 5], s6 = g_esrc[e + 6], s7 = g_esrc[e + 7];
        float4 v0 = loadh(s0), v1 = loadh(s1), v2 = loadh(s2), v3 = loadh(s3);
        float4 v4 = loadh(s4), v5 = loadh(s5), v6 = loadh(s6), v7 = loadh(s7);
        acc.x  += (v0.x + v1.x) + (v2.x + v3.x);
        acc.y  += (v0.y + v1.y) + (v2.y + v3.y);
        acc.z  += (v0.z + v1.z) + (v2.z + v3.z);
        acc.w  += (v0.w + v1.w) + (v2.w + v3.w);
        acc2.x += (v4.x + v5.x) + (v6.x + v7.x);
        acc2.y += (v4.y + v5.y) + (v6.y + v7.y);
        acc2.z += (v4.z + v5.z) + (v6.z + v7.z);
        acc2.w += (v4.w + v5.w) + (v6.w + v7.w);
    }
    for (; e + 3 < end; e += 4) {
        int s0 = g_esrc[e], s1 = g_esrc[e + 1], s2 = g_esrc[e + 2], s3 = g_esrc[e + 3];
        float4 v0 = loadh(s0), v1 = loadh(s1), v2 = loadh(s2), v3 = loadh(s3);
        acc.x += (v0.x + v1.x) + (v2.x + v3.x);
        acc.y += (v0.y + v1.y) + (v2.y + v3.y);
        acc.z += (v0.z + v1.z) + (v2.z + v3.z);
        acc.w += (v0.w + v1.w) + (v2.w + v3.w);
    }
    for (; e < end; e++) {
        float4 v0 = loadh(g_esrc[e]);
        acc.x += v0.x; acc.y += v0.y; acc.z += v0.z; acc.w += v0.w;
    }
    acc.x += acc2.x; acc.y += acc2.y; acc.z += acc2.z; acc.w += acc2.w;

    // self term: h_i, hr-slab write, score segment, pooled
    float4 h = loadh(i);
    reinterpret_cast<float4*>(g_hr + (size_t)i * HRD + (size_t)SLAB * DD)[lane] = h;
    float4 w = reinterpret_cast<const float4*>(aw)[SLAB * 32 + lane];
    float s = h.x * w.x + h.y * w.y + h.z * w.z + h.w * w.w;
#pragma unroll
    for (int off = 16; off; off >>= 1) s += __shfl_down_sync(0xffffffffu, s, off);
    if (lane == 0) {
        if (SLAB == 0) g_scores[i] = s + ab[0];
        else           g_scores[i] += s;
    }
    float sc = 1.0f + eps[SLAB];
    acc.x = fmaf(sc, h.x, acc.x);
    acc.y = fmaf(sc, h.y, acc.y);
    acc.z = fmaf(sc, h.z, acc.z);
    acc.w = fmaf(sc, h.w, acc.w);
    reinterpret_cast<float4*>(g_pooled + (size_t)i * DD)[lane] = acc;
}

// h_4 = relu(affine(z2)) -> hr slab 4; accumulate final score segment (l=3)
__global__ void __launch_bounds__(256) apply_h_kernel(int l,
                                                      const float* __restrict__ aw,
                                                      const float* __restrict__ gamma,
                                                      const float* __restrict__ beta) {
    __shared__ float bnA[DD], bnC[DD];
    int tid = threadIdx.x;
    if (tid < DD) {
        double m = g_sumS[2 * l + 1][tid] / (double)NN;
        double v = g_sumQ[2 * l + 1][tid] / (double)NN - m * m;
        float a = gamma[tid] * rsqrtf((float)(v + (double)BN_EPS));
        bnA[tid] = a;
        bnC[tid] = beta[tid] - (float)m * a;
    }
    __syncthreads();
    int idx = blockIdx.x * blockDim.x + tid;
    if (idx >= NN * 32) return;
    int i = idx >> 5, c = idx & 31;
    float4 z = reinterpret_cast<const float4*>(g_z2 + (size_t)i * DD)[c];
    float4 a = reinterpret_cast<const float4*>(bnA)[c];
    float4 b = reinterpret_cast<const float4*>(bnC)[c];
    float4 o;
    o.x = fmaxf(fmaf(a.x, z.x, b.x), 0.f);
    o.y = fmaxf(fmaf(a.y, z.y, b.y), 0.f);
    o.z = fmaxf(fmaf(a.z, z.z, b.z), 0.f);
    o.w = fmaxf(fmaf(a.w, z.w, b.w), 0.f);
    reinterpret_cast<float4*>(g_hr + (size_t)i * HRD + (size_t)(l + 1) * DD)[c] = o;
    float4 w = reinterpret_cast<const float4*>(aw)[(l + 1) * 32 + c];
    float s = o.x * w.x + o.y * w.y + o.z * w.z + o.w * w.w;
#pragma unroll
    for (int off = 16; off; off >>= 1) s += __shfl_down_sync(0xffffffffu, s, off);
    if ((tid & 31) == 0) g_scores[i] += s;
}

// ---------------- GEMM (176 x 128) @ W[128,128] + b; col stats in fp64 -------
// SECOND=false: A = g_pooled (plain), C = g_z1, stats -> slot 2l
// SECOND=true : A = relu(affine(g_z1)) from slot 2l, C = g_z2, stats -> slot 2l+1
// Mainloop software-pipelines W: next-k LDG issued before current-k FFMA2s.
#define GEMM_SMEM (TILE_R * ASTRIDE * 4 + 2 * DD * 8 + 2 * DD * 4)

template <bool SECOND>
__global__ void __launch_bounds__(256, 2) gemm128_kernel(const float* __restrict__ W,
                                                         const float* __restrict__ bias,
                                                         const float* __restrict__ gamma,
                                                         const float* __restrict__ beta,
                                                         int l) {
    extern __shared__ float smem[];
    float* Ash = smem;                                        // TILE_R x ASTRIDE
    double* redS = reinterpret_cast<double*>(smem + TILE_R * ASTRIDE);
    double* redQ = redS + DD;
    float* bnA = reinterpret_cast<float*>(redQ + DD);
    float* bnC = bnA + DD;

    float* C = SECOND ? g_z2 : g_z1;
    const int slot_out = SECOND ? (2 * l + 1) : (2 * l);

    int tid = threadIdx.x;
    if (tid < DD) {
        redS[tid] = 0.0; redQ[tid] = 0.0;
        if (SECOND) {
            double m = g_sumS[2 * l][tid] / (double)NN;
            double v = g_sumQ[2 * l][tid] / (double)NN - m * m;
            float a = gamma[tid] * rsqrtf((float)(v + (double)BN_EPS));
            bnA[tid] = a;
            bnC[tid] = beta[tid] - (float)m * a;
        }
    }
    __syncthreads();

    int row0 = blockIdx.x * TILE_R;
    {
        const float* A = SECOND ? g_z1 : g_pooled;
#pragma unroll
        for (int ii = 0; ii < TILE_R * 32 / 256; ii++) {
            int i = tid + ii * 256;             // float4 index over tile
            int r = i >> 5, c4 = i & 31;
            int row = row0 + r;
            float4 v = make_float4(0.f, 0.f, 0.f, 0.f);
            if (row < NN) {
                v = *reinterpret_cast<const float4*>(A + (size_t)row * DD + c4 * 4);
                if (SECOND) {
                    float4 ba = reinterpret_cast<const float4*>(bnA)[c4];
                    float4 bc = reinterpret_cast<const float4*>(bnC)[c4];
                    v.x = fmaxf(fmaf(ba.x, v.x, bc.x), 0.f);
                    v.y = fmaxf(fmaf(ba.y, v.y, bc.y), 0.f);
                    v.z = fmaxf(fmaf(ba.z, v.z, bc.z), 0.f);
                    v.w = fmaxf(fmaf(ba.w, v.w, bc.w), 0.f);
                }
            }
            *reinterpret_cast<float4*>(Ash + r * ASTRIDE + c4 * 4) = v;
        }
    }
    __syncthreads();

    int cg = tid & 15;   // 8 columns: 8*cg .. 8*cg+7
    int rg = tid >> 4;   // rows rg*RPT .. rg*RPT+RPT-1
    const float* arow = Ash + rg * RPT * ASTRIDE;
    const ulonglong2* Wg = reinterpret_cast<const ulonglong2*>(W);

    unsigned long long acc[RPT][4];
#pragma unroll
    for (int r = 0; r < RPT; r++)
#pragma unroll
        for (int p = 0; p < 4; p++) acc[r][p] = 0ull;

    // software-pipelined W: prefetch k+1 before computing k
    ulonglong2 wA = __ldg(&Wg[cg * 2]);
    ulonglong2 wB = __ldg(&Wg[cg * 2 + 1]);
#pragma unroll 2
    for (int k = 0; k < DD - 1; k++) {
        ulonglong2 nA = __ldg(&Wg[(k + 1) * 32 + cg * 2]);
        ulonglong2 nB = __ldg(&Wg[(k + 1) * 32 + cg * 2 + 1]);
#pragma unroll
        for (int r = 0; r < RPT; r++) {
            unsigned long long a2 = splat2(arow[r * ASTRIDE + k]);
            ffma2(acc[r][0], a2, wA.x);
            ffma2(acc[r][1], a2, wA.y);
            ffma2(acc[r][2], a2, wB.x);
            ffma2(acc[r][3], a2, wB.y);
        }
        wA = nA; wB = nB;
    }
#pragma unroll
    for (int r = 0; r < RPT; r++) {       // tail k = DD-1
        unsigned long long a2 = splat2(arow[r * ASTRIDE + (DD - 1)]);
        ffma2(acc[r][0], a2, wA.x);
        ffma2(acc[r][1], a2, wA.y);
        ffma2(acc[r][2], a2, wB.x);
        ffma2(acc[r][3], a2, wB.y);
    }

    float bs[8];
#pragma unroll
    for (int j = 0; j < 8; j++) bs[j] = bias[cg * 8 + j];

    float cs[8], cq[8];
#pragma unroll
    for (int j = 0; j < 8; j++) { cs[j] = 0.f; cq[j] = 0.f; }

#pragma unroll
    for (int r = 0; r < RPT; r++) {
        int row = row0 + rg * RPT + r;
        if (row >= NN) continue;
        float o[8];
#pragma unroll
        for (int p = 0; p < 4; p++) {
            float2 u = unpack2(acc[r][p]);
            o[2 * p]     = u.x + bs[2 * p];
            o[2 * p + 1] = u.y + bs[2 * p + 1];
        }
        float4* cp = reinterpret_cast<float4*>(C + (size_t)row * DD + cg * 8);
        cp[0] = make_float4(o[0], o[1], o[2], o[3]);
        cp[1] = make_float4(o[4], o[5], o[6], o[7]);
#pragma unroll
        for (int j = 0; j < 8; j++) {
            cs[j] += o[j];
            cq[j] += o[j] * o[j];
        }
    }
    __syncthreads();
#pragma unroll
    for (int j = 0; j < 8; j++) {
        atomicAdd(&redS[cg * 8 + j], (double)cs[j]);
        atomicAdd(&redQ[cg * 8 + j], (double)cq[j]);
    }
    __syncthreads();
    if (tid < DD) {
        atomicAdd(&g_sumS[slot_out][tid], redS[tid]);
        atomicAdd(&g_sumQ[slot_out][tid], redQ[tid]);
    }
}

// ---------------- attention pooling + head ----------------------------------
// QParts blocks per graph; each computes segment max+denom (redundant, cheap)
// and its 1/QParts share of the weighted sum. Atomic-free.
#define ECHUNK 512
__global__ void __launch_bounds__(256) gemb_part_kernel(const int* __restrict__ gid) {
    __shared__ int s_beg, s_end;
    __shared__ float red[32];
    __shared__ float s_mx, s_dn;
    __shared__ float ecache[ECHUNK];
    int b = blockIdx.x / QParts, q = blockIdx.x % QParts, t = threadIdx.x;
    int lane = t & 31, wid = t >> 5;
    if (t == 0) {
        int lo = 0, hi = NN;
        while (lo < hi) { int m = (lo + hi) >> 1; if (gid[m] < b) lo = m + 1; else hi = m; }
        s_beg = lo;
        lo = 0; hi = NN;
        while (lo < hi) { int m = (lo + hi) >> 1; if (gid[m] < b + 1) lo = m + 1; else hi = m; }
        s_end = lo;
    }
    __syncthreads();
    int beg = s_beg, end = s_end;

    float mx = -CUDART_INF_F;
    for (int i = beg + t; i < end; i += 256) mx = fmaxf(mx, g_scores[i]);
#pragma unroll
    for (int off = 16; off; off >>= 1) mx = fmaxf(mx, __shfl_xor_sync(0xffffffffu, mx, off));
    if (lane == 0) red[wid] = mx;
    __syncthreads();
    if (wid == 0) {
        float m2 = (lane < 8) ? red[lane] : -CUDART_INF_F;
#pragma unroll
        for (int off = 4; off; off >>= 1) m2 = fmaxf(m2, __shfl_xor_sync(0xffffffffu, m2, off));
        if (lane == 0) s_mx = m2;
    }
    __syncthreads();
    float smax = s_mx;

    float dn = 0.f;
    for (int i = beg + t; i < end; i += 256) dn += expf(g_scores[i] - smax);
#pragma unroll
    for (int off = 16; off; off >>= 1) dn += __shfl_xor_sync(0xffffffffu, dn, off);
    if (lane == 0) red[wid] = dn;
    __syncthreads();
    if (wid == 0) {
        float d2 = (lane < 8) ? red[lane] : 0.f;
#pragma unroll
        for (int off = 4; off; off >>= 1) d2 += __shfl_xor_sync(0xffffffffu, d2, off);
        if (lane == 0) s_dn = d2;
    }
    __syncthreads();
    float denom = s_dn;

    int len = end - beg;
    int qb = beg + (int)(((long long)len * q) / QParts);
    int qe = beg + (int)(((long long)len * (q + 1)) / QParts);

    float4 acc = make_float4(0.f, 0.f, 0.f, 0.f);
    for (int chunk = qb; chunk < qe; chunk += ECHUNK) {
        int ce = chunk + ECHUNK < qe ? chunk + ECHUNK : qe;
        for (int i = chunk + t; i < ce; i += 256)
            ecache[i - chunk] = expf(g_scores[i] - smax) / denom;
        __syncthreads();
        if (t < HRD / 4) {
            for (int i = chunk; i < ce; i++) {
                float c = ecache[i - chunk];
                float4 v = reinterpret_cast<const float4*>(g_hr + (size_t)i * HRD)[t];
                acc.x = fmaf(c, v.x, acc.x);
                acc.y = fmaf(c, v.y, acc.y);
                acc.z = fmaf(c, v.z, acc.z);
                acc.w = fmaf(c, v.w, acc.w);
            }
        }
        __syncthreads();
    }
    if (t < HRD / 4)
        reinterpret_cast<float4*>(g_gembp + (size_t)blockIdx.x * HRD)[t] = acc;
}

__global__ void final_kernel(const float* __restrict__ pi,
                             const float* __restrict__ pi_w,
                             const float* __restrict__ pi_b,
                             const float* __restrict__ out_w,
                             const float* __restrict__ out_b,
                             float* __restrict__ out) {
    __shared__ float pie[16];
    int b = blockIdx.x, tid = threadIdx.x;
    if (tid < 16) {
        float a = pi_b[tid];
#pragma unroll
        for (int k = 0; k < 25; k++) a = fmaf(pi[b * 25 + k], pi_w[k * 16 + tid], a);
        pie[tid] = fmaxf(a, 0.f);
    }
    __syncthreads();
    int o = tid >> 5, lane = tid & 31;
    float acc = 0.f;
    const float* gp = g_gembp + (size_t)b * QParts * HRD;
    for (int j = lane; j < HRD; j += 32) {
        float ge = 0.f;
#pragma unroll
        for (int p = 0; p < QParts; p++) ge += gp[p * HRD + j];
        acc = fmaf(ge, out_w[j * NOUT + o], acc);
    }
    if (lane < 16) acc = fmaf(pie[lane], out_w[(HRD + lane) * NOUT + o], acc);
#pragma unroll
    for (int off = 16; off; off >>= 1) acc += __shfl_down_sync(0xffffffffu, acc, off);
    if (lane == 0) out[b * NOUT + o] = acc + out_b[o];
}

// ---------------- launch -----------------------------------------------------
extern "C" void kernel_launch(void* const* d_in, const int* in_sizes, int n_in,
                              void* d_out, int out_size) {
    const float* x    = (const float*)d_in[0];
    const float* pi   = (const float*)d_in[1];
    const float* eps  = (const float*)d_in[2];
    const float* w1   = (const float*)d_in[3];
    const float* b1   = (const float*)d_in[4];
    const float* bng1 = (const float*)d_in[5];
    const float* bnb1 = (const float*)d_in[6];
    const float* w2   = (const float*)d_in[7];
    const float* b2   = (const float*)d_in[8];
    const float* bng  = (const float*)d_in[9];
    const float* bnb  = (const float*)d_in[10];
    const float* aw   = (const float*)d_in[11];
    const float* ab   = (const float*)d_in[12];
    const float* pw   = (const float*)d_in[13];
    const float* pb   = (const float*)d_in[14];
    const float* ow   = (const float*)d_in[15];
    const float* ob   = (const float*)d_in[16];
    const int*   ei   = (const int*)d_in[17];
    const int*   gid  = (const int*)d_in[18];
    const int* src = ei;
    const int* dst = ei + EE;
    float* out = (float*)d_out;

    cudaFuncSetAttribute(gemm128_kernel<false>,
                         cudaFuncAttributeMaxDynamicSharedMemorySize, GEMM_SMEM);
    cudaFuncSetAttribute(gemm128_kernel<true>,
                         cudaFuncAttributeMaxDynamicSharedMemorySize, GEMM_SMEM);

    const int ELT_BLOCKS = (NN * 32 + 255) / 256;          // 6250
    const int GEMM_BLOCKS = (NN + TILE_R - 1) / TILE_R;    // 285
    const int EDGE_BLK = (EE + 255) / 256;                 // 3125

    // ---- CSR by dst; g_cnt==0 at entry; scan zeroes stats + seeds cursors ----
    hist_kernel<<<EDGE_BLK, 256>>>(dst);                   // launch 1
    scan_kernel<<<1, 1024>>>();                            // launch 2
    scatter_kernel<<<EDGE_BLK, 256>>>(src, dst);           // launch 3

    // layer 0
    aggregate_kernel<0><<<ELT_BLOCKS, 256>>>(x, eps, aw, ab, nullptr, nullptr); // launch 4 (profiled)
    gemm128_kernel<false><<<GEMM_BLOCKS, 256, GEMM_SMEM>>>(w1, b1, nullptr, nullptr, 0);
    gemm128_kernel<true><<<GEMM_BLOCKS, 256, GEMM_SMEM>>>(w2, b2, bng1, bnb1, 0);
    // layer 1
    aggregate_kernel<1><<<ELT_BLOCKS, 256>>>(x, eps, aw, ab, bng + 0 * DD, bnb + 0 * DD);
    gemm128_kernel<false><<<GEMM_BLOCKS, 256, GEMM_SMEM>>>(w1 + 1 * DD * DD, b1 + 1 * DD, nullptr, nullptr, 1);
    gemm128_kernel<true><<<GEMM_BLOCKS, 256, GEMM_SMEM>>>(w2 + 1 * DD * DD, b2 + 1 * DD, bng1 + 1 * DD, bnb1 + 1 * DD, 1);
    // layer 2
    aggregate_kernel<2><<<ELT_BLOCKS, 256>>>(x, eps, aw, ab, bng + 1 * DD, bnb + 1 * DD);
    gemm128_kernel<false><<<GEMM_BLOCKS, 256, GEMM_SMEM>>>(w1 + 2 * DD * DD, b1 + 2 * DD, nullptr, nullptr, 2);
    gemm128_kernel<true><<<GEMM_BLOCKS, 256, GEMM_SMEM>>>(w2 + 2 * DD * DD, b2 + 2 * DD, bng1 + 2 * DD, bnb1 + 2 * DD, 2);
    // layer 3
    aggregate_kernel<3><<<ELT_BLOCKS, 256>>>(x, eps, aw, ab, bng + 2 * DD, bnb + 2 * DD);
    gemm128_kernel<false><<<GEMM_BLOCKS, 256, GEMM_SMEM>>>(w1 + 3 * DD * DD, b1 + 3 * DD, nullptr, nullptr, 3);
    gemm128_kernel<true><<<GEMM_BLOCKS, 256, GEMM_SMEM>>>(w2 + 3 * DD * DD, b2 + 3 * DD, bng1 + 3 * DD, bnb1 + 3 * DD, 3);
    // slab 4 (h_4) + final score segment
    apply_h_kernel<<<ELT_BLOCKS, 256>>>(3, aw, bng + 3 * DD, bnb + 3 * DD);

    gemb_part_kernel<<<QParts * BB, 256>>>(gid);
    final_kernel<<<BB, 320>>>(pi, pw, pb, ow, ob, out);
}

// round 17
// speedup vs baseline: 1.3196x; 1.0923x over previous
#include <cuda_runtime.h>
#include <math_constants.h>
#include <math.h>

#define NN 50000
#define EE 800000
#define BB 64
#define DD 128
#define LL 4
#define HRD 640      /* D*(L+1) */
#define NOUT 10
#define BN_EPS 1e-5

#define TILE_R 176   /* 285 blocks @ 2/SM = 0.96 waves; proven family */
#define ASTRIDE 132  /* padded smem row stride: rg groups hit distinct banks */
#define RPT (TILE_R / 16)   /* 11 rows per thread */
#define QParts 16    /* gemb partials per graph */

// ---------------- scratch (device globals; no allocation allowed) ----------
__device__ __align__(16) float  g_hr[(size_t)NN * HRD];   // [x | h1 | h2 | h3 | h4]
__device__ __align__(16) float  g_pooled[NN * DD];
__device__ __align__(16) float  g_z1[NN * DD];
__device__ __align__(16) float  g_z2[NN * DD];
// per-(layer,linear) BN stat slots: [2l] = after mlp_w1, [2l+1] = after mlp_w2
__device__ double g_sumS[2 * LL][DD];
__device__ double g_sumQ[2 * LL][DD];
__device__ float  g_scores[NN];
__device__ __align__(16) float  g_gembp[QParts * BB * HRD];  // partials per graph
// CSR scratch. Invariants across calls (graph replays):
//   g_cnt == 0 at call entry (zeroed by scan each call; zero at module load)
//   g_cur is seeded to rowptr by scan each call BEFORE scatter uses it
__device__ int g_cnt[NN];
__device__ int g_cur[NN];
__device__ int g_rowptr[NN + 1];
__device__ int g_esrc[EE];

// ---------------- packed f32x2 helpers (Blackwell) --------------------------
__device__ __forceinline__ void ffma2(unsigned long long& acc,
                                      unsigned long long a,
                                      unsigned long long b) {
    asm("fma.rn.f32x2 %0, %1, %2, %0;" : "+l"(acc) : "l"(a), "l"(b));
}
__device__ __forceinline__ unsigned long long splat2(float a) {
    unsigned long long r;
    asm("mov.b64 %0, {%1, %1};" : "=l"(r) : "f"(a));
    return r;
}
__device__ __forceinline__ float2 unpack2(unsigned long long v) {
    float2 r;
    asm("mov.b64 {%0, %1}, %2;" : "=f"(r.x), "=f"(r.y) : "l"(v));
    return r;
}

// ---------------- CSR construction ------------------------------------------
__global__ void hist_kernel(const int* __restrict__ dst) {
    int e = blockIdx.x * blockDim.x + threadIdx.x;
    if (e < EE) atomicAdd(&g_cnt[dst[e]], 1);
}

// single-block hierarchical scan over 50000 counts.
// Writes rowptr, seeds g_cur = rowptr, zeroes g_cnt, zeroes BN stat slots.
__global__ void __launch_bounds__(1024) scan_kernel() {
    __shared__ int wsum[32];
    __shared__ int carry_sh;
    int tid = threadIdx.x, lane = tid & 31, wid = tid >> 5;
    // zero BN stat slots (deterministic per call -> replay safe)
    for (int i = tid; i < 2 * LL * DD; i += 1024) {
        (&g_sumS[0][0])[i] = 0.0;
        (&g_sumQ[0][0])[i] = 0.0;
    }
    if (tid == 0) carry_sh = 0;
    __syncthreads();
    for (int t = 0; t < 49; t++) {
        int g = t * 1024 + tid;
        int v = (g < NN) ? g_cnt[g] : 0;
        if (g < NN) g_cnt[g] = 0;
        int carry = carry_sh;
        int s = v;
#pragma unroll
        for (int off = 1; off < 32; off <<= 1) {
            int u = __shfl_up_sync(0xffffffffu, s, off);
            if (lane >= off) s += u;
        }
        if (lane == 31) wsum[wid] = s;
        __syncthreads();
        if (wid == 0) {
            int ws = wsum[lane];
#pragma unroll
            for (int off = 1; off < 32; off <<= 1) {
                int u = __shfl_up_sync(0xffffffffu, ws, off);
                if (lane >= off) ws += u;
            }
            wsum[lane] = ws;
        }
        __syncthreads();
        int wpre = (wid == 0) ? 0 : wsum[wid - 1];
        if (g < NN) {
            int rp = carry + wpre + s - v;
            g_rowptr[g] = rp;
            g_cur[g] = rp;          // scatter cursor seeded fresh every call
        }
        __syncthreads();
        if (tid == 1023) carry_sh = carry + wsum[31];
        __syncthreads();
    }
    if (tid == 0) g_rowptr[NN] = EE;
}

__global__ void scatter_kernel(const int* __restrict__ src,
                               const int* __restrict__ dst) {
    int e = blockIdx.x * blockDim.x + threadIdx.x;
    if (e >= EE) return;
    int d = dst[e];
    int p = atomicAdd(&g_cur[d], 1);   // cursor pre-seeded to rowptr[d]
    g_esrc[p] = src[e];
}

// ---------------- fused aggregation ------------------------------------------
// aggregate<SLAB>:
//   SLAB==0: h = x (passthrough).   SLAB>=1: h = relu(bnA*z2 + bnC) on the fly
// For node i: pooled[i] = sum_nbr h[src] + (1+eps[SLAB])*h[i];
// writes h[i] into hr slab SLAB; accumulates attention score segment.
// Edge loop unrolled 8-deep (two 4-trees) for MLP against L2 latency.
template <int SLAB>
__global__ void __launch_bounds__(256) aggregate_kernel(
    const float* __restrict__ x, const float* __restrict__ eps,
    const float* __restrict__ aw, const float* __restrict__ ab,
    const float* __restrict__ gamma, const float* __restrict__ beta) {
    __shared__ float bnA[DD], bnC[DD];
    int tid = threadIdx.x;
    if (SLAB > 0) {
        if (tid < DD) {
            double m = g_sumS[2 * (SLAB - 1) + 1][tid] / (double)NN;
            double v = g_sumQ[2 * (SLAB - 1) + 1][tid] / (double)NN - m * m;
            float a = gamma[tid] * rsqrtf((float)(v + (double)BN_EPS));
            bnA[tid] = a;
            bnC[tid] = beta[tid] - (float)m * a;
        }
        __syncthreads();
    }
    int idx = blockIdx.x * 256 + tid;
    int i = idx >> 5, lane = idx & 31;
    if (i >= NN) return;

    float4 a4, c4;
    if (SLAB > 0) {
        a4 = reinterpret_cast<const float4*>(bnA)[lane];
        c4 = reinterpret_cast<const float4*>(bnC)[lane];
    }
    const float* hsrc = (SLAB == 0) ? x : g_z2;

    auto loadh = [&](int s) -> float4 {
        float4 v = reinterpret_cast<const float4*>(hsrc + (size_t)s * DD)[lane];
        if (SLAB > 0) {
            v.x = fmaxf(fmaf(a4.x, v.x, c4.x), 0.f);
            v.y = fmaxf(fmaf(a4.y, v.y, c4.y), 0.f);
            v.z = fmaxf(fmaf(a4.z, v.z, c4.z), 0.f);
            v.w = fmaxf(fmaf(a4.w, v.w, c4.w), 0.f);
        }
        return v;
    };

    int beg = g_rowptr[i], end = g_rowptr[i + 1];
    float4 acc = make_float4(0.f, 0.f, 0.f, 0.f);
    float4 acc2 = make_float4(0.f, 0.f, 0.f, 0.f);
    int e = beg;
    for (; e + 7 < end; e += 8) {
        int s0 = g_esrc[e],     s1 = g_esrc[e + 1], s2 = g_esrc[e + 2], s3 = g_esrc[e + 3];
        int s4 = g_esrc[e + 4], s5 = g_esrc[e + 5], s6 = g_esrc[e + 6], s7 = g_esrc[e + 7];
        float4 v0 = loadh(s0), v1 = loadh(s1), v2 = loadh(s2), v3 = loadh(s3);
        float4 v4 = loadh(s4), v5 = loadh(s5), v6 = loadh(s6), v7 = loadh(s7);
        acc.x  += (v0.x + v1.x) + (v2.x + v3.x);
        acc.y  += (v0.y + v1.y) + (v2.y + v3.y);
        acc.z  += (v0.z + v1.z) + (v2.z + v3.z);
        acc.w  += (v0.w + v1.w) + (v2.w + v3.w);
        acc2.x += (v4.x + v5.x) + (v6.x + v7.x);
        acc2.y += (v4.y + v5.y) + (v6.y + v7.y);
        acc2.z += (v4.z + v5.z) + (v6.z + v7.z);
        acc2.w += (v4.w + v5.w) + (v6.w + v7.w);
    }
    for (; e + 3 < end; e += 4) {
        int s0 = g_esrc[e], s1 = g_esrc[e + 1], s2 = g_esrc[e + 2], s3 = g_esrc[e + 3];
        float4 v0 = loadh(s0), v1 = loadh(s1), v2 = loadh(s2), v3 = loadh(s3);
        acc.x += (v0.x + v1.x) + (v2.x + v3.x);
        acc.y += (v0.y + v1.y) + (v2.y + v3.y);
        acc.z += (v0.z + v1.z) + (v2.z + v3.z);
        acc.w += (v0.w + v1.w) + (v2.w + v3.w);
    }
    for (; e < end; e++) {
        float4 v0 = loadh(g_esrc[e]);
        acc.x += v0.x; acc.y += v0.y; acc.z += v0.z; acc.w += v0.w;
    }
    acc.x += acc2.x; acc.y += acc2.y; acc.z += acc2.z; acc.w += acc2.w;

    // self term: h_i, hr-slab write, score segment, pooled
    float4 h = loadh(i);
    reinterpret_cast<float4*>(g_hr + (size_t)i * HRD + (size_t)SLAB * DD)[lane] = h;
    float4 w = reinterpret_cast<const float4*>(aw)[SLAB * 32 + lane];
    float s = h.x * w.x + h.y * w.y + h.z * w.z + h.w * w.w;
#pragma unroll
    for (int off = 16; off; off >>= 1) s += __shfl_down_sync(0xffffffffu, s, off);
    if (lane == 0) {
        if (SLAB == 0) g_scores[i] = s + ab[0];
        else           g_scores[i] += s;
    }
    float sc = 1.0f + eps[SLAB];
    acc.x = fmaf(sc, h.x, acc.x);
    acc.y = fmaf(sc, h.y, acc.y);
    acc.z = fmaf(sc, h.z, acc.z);
    acc.w = fmaf(sc, h.w, acc.w);
    reinterpret_cast<float4*>(g_pooled + (size_t)i * DD)[lane] = acc;
}

// h_4 = relu(affine(z2)) -> hr slab 4; accumulate final score segment (l=3)
__global__ void __launch_bounds__(256) apply_h_kernel(int l,
                                                      const float* __restrict__ aw,
                                                      const float* __restrict__ gamma,
                                                      const float* __restrict__ beta) {
    __shared__ float bnA[DD], bnC[DD];
    int tid = threadIdx.x;
    if (tid < DD) {
        double m = g_sumS[2 * l + 1][tid] / (double)NN;
        double v = g_sumQ[2 * l + 1][tid] / (double)NN - m * m;
        float a = gamma[tid] * rsqrtf((float)(v + (double)BN_EPS));
        bnA[tid] = a;
        bnC[tid] = beta[tid] - (float)m * a;
    }
    __syncthreads();
    int idx = blockIdx.x * blockDim.x + tid;
    if (idx >= NN * 32) return;
    int i = idx >> 5, c = idx & 31;
    float4 z = reinterpret_cast<const float4*>(g_z2 + (size_t)i * DD)[c];
    float4 a = reinterpret_cast<const float4*>(bnA)[c];
    float4 b = reinterpret_cast<const float4*>(bnC)[c];
    float4 o;
    o.x = fmaxf(fmaf(a.x, z.x, b.x), 0.f);
    o.y = fmaxf(fmaf(a.y, z.y, b.y), 0.f);
    o.z = fmaxf(fmaf(a.z, z.z, b.z), 0.f);
    o.w = fmaxf(fmaf(a.w, z.w, b.w), 0.f);
    reinterpret_cast<float4*>(g_hr + (size_t)i * HRD + (size_t)(l + 1) * DD)[c] = o;
    float4 w = reinterpret_cast<const float4*>(aw)[(l + 1) * 32 + c];
    float s = o.x * w.x + o.y * w.y + o.z * w.z + o.w * w.w;
#pragma unroll
    for (int off = 16; off; off >>= 1) s += __shfl_down_sync(0xffffffffu, s, off);
    if ((tid & 31) == 0) g_scores[i] += s;
}

// ---------------- GEMM (176 x 128) @ W[128,128] + b; col stats in fp64 -------
// SECOND=false: A = g_pooled (plain), C = g_z1, stats -> slot 2l
// SECOND=true : A = relu(affine(g_z1)) from slot 2l, C = g_z2, stats -> slot 2l+1
// Mainloop software-pipelines W: next-k LDG issued before current-k FFMA2s.
#define GEMM_SMEM (TILE_R * ASTRIDE * 4 + 2 * DD * 8 + 2 * DD * 4)

template <bool SECOND>
__global__ void __launch_bounds__(256, 2) gemm128_kernel(const float* __restrict__ W,
                                                         const float* __restrict__ bias,
                                                         const float* __restrict__ gamma,
                                                         const float* __restrict__ beta,
                                                         int l) {
    extern __shared__ float smem[];
    float* Ash = smem;                                        // TILE_R x ASTRIDE
    double* redS = reinterpret_cast<double*>(smem + TILE_R * ASTRIDE);
    double* redQ = redS + DD;
    float* bnA = reinterpret_cast<float*>(redQ + DD);
    float* bnC = bnA + DD;

    float* C = SECOND ? g_z2 : g_z1;
    const int slot_out = SECOND ? (2 * l + 1) : (2 * l);

    int tid = threadIdx.x;
    if (tid < DD) {
        redS[tid] = 0.0; redQ[tid] = 0.0;
        if (SECOND) {
            double m = g_sumS[2 * l][tid] / (double)NN;
            double v = g_sumQ[2 * l][tid] / (double)NN - m * m;
            float a = gamma[tid] * rsqrtf((float)(v + (double)BN_EPS));
            bnA[tid] = a;
            bnC[tid] = beta[tid] - (float)m * a;
        }
    }
    __syncthreads();

    int row0 = blockIdx.x * TILE_R;
    {
        const float* A = SECOND ? g_z1 : g_pooled;
#pragma unroll
        for (int ii = 0; ii < TILE_R * 32 / 256; ii++) {
            int i = tid + ii * 256;             // float4 index over tile
            int r = i >> 5, c4 = i & 31;
            int row = row0 + r;
            float4 v = make_float4(0.f, 0.f, 0.f, 0.f);
            if (row < NN) {
                v = *reinterpret_cast<const float4*>(A + (size_t)row * DD + c4 * 4);
                if (SECOND) {
                    float4 ba = reinterpret_cast<const float4*>(bnA)[c4];
                    float4 bc = reinterpret_cast<const float4*>(bnC)[c4];
                    v.x = fmaxf(fmaf(ba.x, v.x, bc.x), 0.f);
                    v.y = fmaxf(fmaf(ba.y, v.y, bc.y), 0.f);
                    v.z = fmaxf(fmaf(ba.z, v.z, bc.z), 0.f);
                    v.w = fmaxf(fmaf(ba.w, v.w, bc.w), 0.f);
                }
            }
            *reinterpret_cast<float4*>(Ash + r * ASTRIDE + c4 * 4) = v;
        }
    }
    __syncthreads();

    int cg = tid & 15;   // 8 columns: 8*cg .. 8*cg+7
    int rg = tid >> 4;   // rows rg*RPT .. rg*RPT+RPT-1
    const float* arow = Ash + rg * RPT * ASTRIDE;
    const ulonglong2* Wg = reinterpret_cast<const ulonglong2*>(W);

    unsigned long long acc[RPT][4];
#pragma unroll
    for (int r = 0; r < RPT; r++)
#pragma unroll
        for (int p = 0; p < 4; p++) acc[r][p] = 0ull;

    // software-pipelined W: prefetch k+1 before computing k
    ulonglong2 wA = __ldg(&Wg[cg * 2]);
    ulonglong2 wB = __ldg(&Wg[cg * 2 + 1]);
#pragma unroll 2
    for (int k = 0; k < DD - 1; k++) {
        ulonglong2 nA = __ldg(&Wg[(k + 1) * 32 + cg * 2]);
        ulonglong2 nB = __ldg(&Wg[(k + 1) * 32 + cg * 2 + 1]);
#pragma unroll
        for (int r = 0; r < RPT; r++) {
            unsigned long long a2 = splat2(arow[r * ASTRIDE + k]);
            ffma2(acc[r][0], a2, wA.x);
            ffma2(acc[r][1], a2, wA.y);
            ffma2(acc[r][2], a2, wB.x);
            ffma2(acc[r][3], a2, wB.y);
        }
        wA = nA; wB = nB;
    }
#pragma unroll
    for (int r = 0; r < RPT; r++) {       // tail k = DD-1
        unsigned long long a2 = splat2(arow[r * ASTRIDE + (DD - 1)]);
        ffma2(acc[r][0], a2, wA.x);
        ffma2(acc[r][1], a2, wA.y);
        ffma2(acc[r][2], a2, wB.x);
        ffma2(acc[r][3], a2, wB.y);
    }

    float bs[8];
#pragma unroll
    for (int j = 0; j < 8; j++) bs[j] = bias[cg * 8 + j];

    float cs[8], cq[8];
#pragma unroll
    for (int j = 0; j < 8; j++) { cs[j] = 0.f; cq[j] = 0.f; }

#pragma unroll
    for (int r = 0; r < RPT; r++) {
        int row = row0 + rg * RPT + r;
        if (row >= NN) continue;
        float o[8];
#pragma unroll
        for (int p = 0; p < 4; p++) {
            float2 u = unpack2(acc[r][p]);
            o[2 * p]     = u.x + bs[2 * p];
            o[2 * p + 1] = u.y + bs[2 * p + 1];
        }
        float4* cp = reinterpret_cast<float4*>(C + (size_t)row * DD + cg * 8);
        cp[0] = make_float4(o[0], o[1], o[2], o[3]);
        cp[1] = make_float4(o[4], o[5], o[6], o[7]);
#pragma unroll
        for (int j = 0; j < 8; j++) {
            cs[j] += o[j];
            cq[j] += o[j] * o[j];
        }
    }
    // lanes L and L+16 share the same cg -> pre-reduce, halve atomic traffic
#pragma unroll
    for (int j = 0; j < 8; j++) {
        cs[j] += __shfl_down_sync(0xffffffffu, cs[j], 16);
        cq[j] += __shfl_down_sync(0xffffffffu, cq[j], 16);
    }
    __syncthreads();
    if ((tid & 31) < 16) {
#pragma unroll
        for (int j = 0; j < 8; j++) {
            atomicAdd(&redS[cg * 8 + j], (double)cs[j]);
            atomicAdd(&redQ[cg * 8 + j], (double)cq[j]);
        }
    }
    __syncthreads();
    if (tid < DD) {
        atomicAdd(&g_sumS[slot_out][tid], redS[tid]);
        atomicAdd(&g_sumQ[slot_out][tid], redQ[tid]);
    }
}

// ---------------- attention pooling + head ----------------------------------
// QParts blocks per graph; each computes segment max+denom (redundant, cheap)
// and its 1/QParts share of the weighted sum. Atomic-free.
#define ECHUNK 512
__global__ void __launch_bounds__(256) gemb_part_kernel(const int* __restrict__ gid) {
    __shared__ int s_beg, s_end;
    __shared__ float red[32];
    __shared__ float s_mx, s_dn;
    __shared__ float ecache[ECHUNK];
    int b = blockIdx.x / QParts, q = blockIdx.x % QParts, t = threadIdx.x;
    int lane = t & 31, wid = t >> 5;
    if (t == 0) {
        int lo = 0, hi = NN;
        while (lo < hi) { int m = (lo + hi) >> 1; if (gid[m] < b) lo = m + 1; else hi = m; }
        s_beg = lo;
        lo = 0; hi = NN;
        while (lo < hi) { int m = (lo + hi) >> 1; if (gid[m] < b + 1) lo = m + 1; else hi = m; }
        s_end = lo;
    }
    __syncthreads();
    int beg = s_beg, end = s_end;

    float mx = -CUDART_INF_F;
    for (int i = beg + t; i < end; i += 256) mx = fmaxf(mx, g_scores[i]);
#pragma unroll
    for (int off = 16; off; off >>= 1) mx = fmaxf(mx, __shfl_xor_sync(0xffffffffu, mx, off));
    if (lane == 0) red[wid] = mx;
    __syncthreads();
    if (wid == 0) {
        float m2 = (lane < 8) ? red[lane] : -CUDART_INF_F;
#pragma unroll
        for (int off = 4; off; off >>= 1) m2 = fmaxf(m2, __shfl_xor_sync(0xffffffffu, m2, off));
        if (lane == 0) s_mx = m2;
    }
    __syncthreads();
    float smax = s_mx;

    float dn = 0.f;
    for (int i = beg + t; i < end; i += 256) dn += expf(g_scores[i] - smax);
#pragma unroll
    for (int off = 16; off; off >>= 1) dn += __shfl_xor_sync(0xffffffffu, dn, off);
    if (lane == 0) red[wid] = dn;
    __syncthreads();
    if (wid == 0) {
        float d2 = (lane < 8) ? red[lane] : 0.f;
#pragma unroll
        for (int off = 4; off; off >>= 1) d2 += __shfl_xor_sync(0xffffffffu, d2, off);
        if (lane == 0) s_dn = d2;
    }
    __syncthreads();
    float denom = s_dn;

    int len = end - beg;
    int qb = beg + (int)(((long long)len * q) / QParts);
    int qe = beg + (int)(((long long)len * (q + 1)) / QParts);

    float4 acc = make_float4(0.f, 0.f, 0.f, 0.f);
    for (int chunk = qb; chunk < qe; chunk += ECHUNK) {
        int ce = chunk + ECHUNK < qe ? chunk + ECHUNK : qe;
        for (int i = chunk + t; i < ce; i += 256)
            ecache[i - chunk] = expf(g_scores[i] - smax) / denom;
        __syncthreads();
        if (t < HRD / 4) {
            for (int i = chunk; i < ce; i++) {
                float c = ecache[i - chunk];
                float4 v = reinterpret_cast<const float4*>(g_hr + (size_t)i * HRD)[t];
                acc.x = fmaf(c, v.x, acc.x);
                acc.y = fmaf(c, v.y, acc.y);
                acc.z = fmaf(c, v.z, acc.z);
                acc.w = fmaf(c, v.w, acc.w);
            }
        }
        __syncthreads();
    }
    if (t < HRD / 4)
        reinterpret_cast<float4*>(g_gembp + (size_t)blockIdx.x * HRD)[t] = acc;
}

__global__ void final_kernel(const float* __restrict__ pi,
                             const float* __restrict__ pi_w,
                             const float* __restrict__ pi_b,
                             const float* __restrict__ out_w,
                             const float* __restrict__ out_b,
                             float* __restrict__ out) {
    __shared__ float pie[16];
    int b = blockIdx.x, tid = threadIdx.x;
    if (tid < 16) {
        float a = pi_b[tid];
#pragma unroll
        for (int k = 0; k < 25; k++) a = fmaf(pi[b * 25 + k], pi_w[k * 16 + tid], a);
        pie[tid] = fmaxf(a, 0.f);
    }
    __syncthreads();
    int o = tid >> 5, lane = tid & 31;
    float acc = 0.f;
    const float* gp = g_gembp + (size_t)b * QParts * HRD;
    for (int j = lane; j < HRD; j += 32) {
        float ge = 0.f;
#pragma unroll
        for (int p = 0; p < QParts; p++) ge += gp[p * HRD + j];
        acc = fmaf(ge, out_w[j * NOUT + o], acc);
    }
    if (lane < 16) acc = fmaf(pie[lane], out_w[(HRD + lane) * NOUT + o], acc);
#pragma unroll
    for (int off = 16; off; off >>= 1) acc += __shfl_down_sync(0xffffffffu, acc, off);
    if (lane == 0) out[b * NOUT + o] = acc + out_b[o];
}

// ---------------- launch -----------------------------------------------------
extern "C" void kernel_launch(void* const* d_in, const int* in_sizes, int n_in,
                              void* d_out, int out_size) {
    const float* x    = (const float*)d_in[0];
    const float* pi   = (const float*)d_in[1];
    const float* eps  = (const float*)d_in[2];
    const float* w1   = (const float*)d_in[3];
    const float* b1   = (const float*)d_in[4];
    const float* bng1 = (const float*)d_in[5];
    const float* bnb1 = (const float*)d_in[6];
    const float* w2   = (const float*)d_in[7];
    const float* b2   = (const float*)d_in[8];
    const float* bng  = (const float*)d_in[9];
    const float* bnb  = (const float*)d_in[10];
    const float* aw   = (const float*)d_in[11];
    const float* ab   = (const float*)d_in[12];
    const float* pw   = (const float*)d_in[13];
    const float* pb   = (const float*)d_in[14];
    const float* ow   = (const float*)d_in[15];
    const float* ob   = (const float*)d_in[16];
    const int*   ei   = (const int*)d_in[17];
    const int*   gid  = (const int*)d_in[18];
    const int* src = ei;
    const int* dst = ei + EE;
    float* out = (float*)d_out;

    cudaFuncSetAttribute(gemm128_kernel<false>,
                         cudaFuncAttributeMaxDynamicSharedMemorySize, GEMM_SMEM);
    cudaFuncSetAttribute(gemm128_kernel<true>,
                         cudaFuncAttributeMaxDynamicSharedMemorySize, GEMM_SMEM);

    const int ELT_BLOCKS = (NN * 32 + 255) / 256;          // 6250
    const int GEMM_BLOCKS = (NN + TILE_R - 1) / TILE_R;    // 285
    const int EDGE_BLK = (EE + 255) / 256;                 // 3125

    // ---- CSR by dst; g_cnt==0 at entry; scan zeroes stats + seeds cursors ----
    hist_kernel<<<EDGE_BLK, 256>>>(dst);                   // launch 1
    scan_kernel<<<1, 1024>>>();                            // launch 2
    scatter_kernel<<<EDGE_BLK, 256>>>(src, dst);           // launch 3

    // layer 0
    aggregate_kernel<0><<<ELT_BLOCKS, 256>>>(x, eps, aw, ab, nullptr, nullptr); // launch 4 (profiled)
    gemm128_kernel<false><<<GEMM_BLOCKS, 256, GEMM_SMEM>>>(w1, b1, nullptr, nullptr, 0);
    gemm128_kernel<true><<<GEMM_BLOCKS, 256, GEMM_SMEM>>>(w2, b2, bng1, bnb1, 0);
    // layer 1
    aggregate_kernel<1><<<ELT_BLOCKS, 256>>>(x, eps, aw, ab, bng + 0 * DD, bnb + 0 * DD);
    gemm128_kernel<false><<<GEMM_BLOCKS, 256, GEMM_SMEM>>>(w1 + 1 * DD * DD, b1 + 1 * DD, nullptr, nullptr, 1);
    gemm128_kernel<true><<<GEMM_BLOCKS, 256, GEMM_SMEM>>>(w2 + 1 * DD * DD, b2 + 1 * DD, bng1 + 1 * DD, bnb1 + 1 * DD, 1);
    // layer 2
    aggregate_kernel<2><<<ELT_BLOCKS, 256>>>(x, eps, aw, ab, bng + 1 * DD, bnb + 1 * DD);
    gemm128_kernel<false><<<GEMM_BLOCKS, 256, GEMM_SMEM>>>(w1 + 2 * DD * DD, b1 + 2 * DD, nullptr, nullptr, 2);
    gemm128_kernel<true><<<GEMM_BLOCKS, 256, GEMM_SMEM>>>(w2 + 2 * DD * DD, b2 + 2 * DD, bng1 + 2 * DD, bnb1 + 2 * DD, 2);
    // layer 3
    aggregate_kernel<3><<<ELT_BLOCKS, 256>>>(x, eps, aw, ab, bng + 2 * DD, bnb + 2 * DD);
    gemm128_kernel<false><<<GEMM_BLOCKS, 256, GEMM_SMEM>>>(w1 + 3 * DD * DD, b1 + 3 * DD, nullptr, nullptr, 3);
    gemm128_kernel<true><<<GEMM_BLOCKS, 256, GEMM_SMEM>>>(w2 + 3 * DD * DD, b2 + 3 * DD, bng1 + 3 * DD, bnb1 + 3 * DD, 3);
    // slab 4 (h_4) + final score segment
    apply_h_kernel<<<ELT_BLOCKS, 256>>>(3, aw, bng + 3 * DD, bnb + 3 * DD);

    gemb_part_kernel<<<QParts * BB, 256>>>(gid);
    final_kernel<<<BB, 320>>>(pi, pw, pb, ow, ob, out);
}